// round 8
// baseline (speedup 1.0000x reference)
#include <cuda_runtime.h>
#include <cuda_bf16.h>
#include <stdint.h>
#include <math.h>

#define TT 512
#define BB 256
#define FF 512
#define HH 512
#define NCTA 128
#define NTH 512
#define ZP 144

// W in mma-fragment order: [mt 32][wm 4][kstep 64][split 2][lane 32] x uint4
__device__ uint4 g_Wf[32 * 4 * 64 * 2 * 32];
// gx = x*Wih^T + biases, fragment order: [t][cid 128][wid 16] -> 256 floats
__device__ float g_gx[512L * 128 * 16 * 256];
__device__ __nv_bfloat16 g_hhi[2][BB * HH];
__device__ __nv_bfloat16 g_hlo[2][BB * HH];
__device__ unsigned g_flag[4][32];   // [nt][mt]: steps completed

__device__ __forceinline__ unsigned pack2(float a, float b) {
    __nv_bfloat162 t; t.x = __float2bfloat16_rn(a); t.y = __float2bfloat16_rn(b);
    return *(unsigned*)&t;
}
__device__ __forceinline__ float sig_fast(float v) {
    return __fdividef(1.0f, 1.0f + __expf(-v));
}
__device__ __forceinline__ float tanh_fast(float v) {
    float e = __expf(-2.0f * fabsf(v));
    return copysignf(__fdividef(1.0f - e, 1.0f + e), v);
}

#define MMA(c, a, b0, b1) \
    asm volatile("mma.sync.aligned.m16n8k16.row.col.f32.bf16.bf16.f32 " \
        "{%0,%1,%2,%3}, {%4,%5,%6,%7}, {%8,%9}, {%0,%1,%2,%3};" \
        : "+f"((c)[0]), "+f"((c)[1]), "+f"((c)[2]), "+f"((c)[3]) \
        : "r"((a).x), "r"((a).y), "r"((a).z), "r"((a).w), "r"(b0), "r"(b1))

// ---- phase 0: W gather/split to fragment order; zero h0; reset flags ----
__global__ void phase0(const float* __restrict__ wih, const float* __restrict__ whh) {
    long id = (long)blockIdx.x * blockDim.x + threadIdx.x;
    long stride = (long)gridDim.x * blockDim.x;
    for (long i = id; i < 32L * 4 * 64 * 2 * 32; i += stride) {
        int lane = (int)(i & 31);
        long r1 = i >> 5;
        int split = (int)(r1 & 1);
        long r2 = r1 >> 1;
        int kstep = (int)(r2 & 63);
        long r3 = r2 >> 6;
        int wm = (int)(r3 & 3);
        int mt = (int)(r3 >> 2);
        int g = lane >> 2, c4 = lane & 3;
        int ka = kstep * 16 + 2 * c4;
        float e[2][4];
        #pragma unroll
        for (int rr = 0; rr < 2; ++rr) {
            int r = wm * 16 + g + rr * 8;
            int orig = (r >> 4) * 512 + mt * 16 + (r & 15);
            #pragma unroll
            for (int kk = 0; kk < 4; ++kk) {
                int k = ka + (kk & 1) + (kk >> 1) * 8;
                float v = (k < 512) ? wih[(long)orig * 512 + k]
                                    : whh[(long)orig * 512 + k - 512];
                float hv = __bfloat162float(__float2bfloat16_rn(v));
                e[rr][kk] = split ? (v - hv) : v;
            }
        }
        uint4 o;
        o.x = pack2(e[0][0], e[0][1]);
        o.y = pack2(e[1][0], e[1][1]);
        o.z = pack2(e[0][2], e[0][3]);
        o.w = pack2(e[1][2], e[1][3]);
        g_Wf[i] = o;
    }
    __nv_bfloat16 z = __float2bfloat16_rn(0.0f);
    for (long i = id; i < (long)BB * HH; i += stride) { g_hhi[0][i] = z; g_hlo[0][i] = z; }
    if (id < 128) ((unsigned*)g_flag)[id] = 0;
}

// ---- phase 1: gx[t] = x_t * Wih^T + biases, fragment order ----
__global__ void __launch_bounds__(NTH, 1) phase1(
    const float* __restrict__ x,
    const float* __restrict__ bih,
    const float* __restrict__ bhh)
{
    __shared__ __align__(16) char zs[2][2][64 * ZP];
    const int tid = threadIdx.x;
    const int wid = tid >> 5;
    const int lane = tid & 31;
    const int g = lane >> 2, c4 = lane & 3;
    const int wm = wid >> 2, wn = wid & 3;     // 4 M-subtiles x 4 N-subtiles
    const int cid = blockIdx.x & 127;
    const int tg = blockIdx.x >> 7;            // 0..15, 32 steps each
    const int mt = cid >> 2, nt = cid & 3;
    const int b0 = nt * 64;
    const uint4* __restrict__ wf = g_Wf + (long)(mt * 4 + wm) * 64 * 2 * 32;

    const int r0 = wm * 16 + g, r1 = r0 + 8;
    const int o0 = (r0 >> 4) * 512 + mt * 16 + (r0 & 15);
    const int o1 = (r1 >> 4) * 512 + mt * 16 + (r1 & 15);
    const float b_r0 = bih[o0] + bhh[o0];
    const float b_r1 = bih[o1] + bhh[o1];

    for (int i = 0; i < 32; ++i) {
        const int t = tg * 32 + i;
        float acc[2][4];
        #pragma unroll
        for (int n2 = 0; n2 < 2; ++n2) {
            acc[n2][0] = b_r0; acc[n2][1] = b_r0;
            acc[n2][2] = b_r1; acc[n2][3] = b_r1;
        }
        const float* xs0 = x + ((long)t * BB + b0) * FF;
        #pragma unroll
        for (int it = 0; it < 2; ++it) {
            int u = tid + it * 512;
            int row = u >> 4, k0 = (u & 15) * 4;
            float4 v = *(const float4*)(xs0 + (long)row * FF + k0);
            float hx = __bfloat162float(__float2bfloat16_rn(v.x));
            float hy = __bfloat162float(__float2bfloat16_rn(v.y));
            float hz = __bfloat162float(__float2bfloat16_rn(v.z));
            float hw = __bfloat162float(__float2bfloat16_rn(v.w));
            *(uint2*)(zs[0][0] + row * ZP + k0 * 2) = make_uint2(pack2(hx, hy), pack2(hz, hw));
            *(uint2*)(zs[0][1] + row * ZP + k0 * 2) =
                make_uint2(pack2(v.x - hx, v.y - hy), pack2(v.z - hz, v.w - hw));
        }
        __syncthreads();

        for (int kc = 0; kc < 8; ++kc) {
            const int buf = kc & 1;
            const int nk = kc + 1;
            float4 p0, p1;
            if (nk < 8) {
                const float* xs = xs0 + nk * 64;
                int u0 = tid, u1 = tid + 512;
                p0 = *(const float4*)(xs + (long)(u0 >> 4) * FF + (u0 & 15) * 4);
                p1 = *(const float4*)(xs + (long)(u1 >> 4) * FF + (u1 & 15) * 4);
            }
            {
                const uint4* wfb = wf + (long)(kc * 4) * 2 * 32;
                const char* zb0 = zs[buf][0];
                const char* zb1 = zs[buf][1];
                #pragma unroll
                for (int ks = 0; ks < 4; ++ks) {
                    uint4 Ah = __ldg(&wfb[(ks * 2 + 0) * 32 + lane]);
                    uint4 Al = __ldg(&wfb[(ks * 2 + 1) * 32 + lane]);
                    const char* zh = zb0 + ks * 32 + c4 * 4;
                    const char* zl = zb1 + ks * 32 + c4 * 4;
                    #pragma unroll
                    for (int n2 = 0; n2 < 2; ++n2) {
                        const int noff = (wn * 16 + n2 * 8 + g) * ZP;
                        unsigned bh0 = *(const unsigned*)(zh + noff);
                        unsigned bh1 = *(const unsigned*)(zh + noff + 16);
                        unsigned bl0 = *(const unsigned*)(zl + noff);
                        unsigned bl1 = *(const unsigned*)(zl + noff + 16);
                        MMA(acc[n2], Ah, bh0, bh1);
                        MMA(acc[n2], Ah, bl0, bl1);
                        MMA(acc[n2], Al, bh0, bh1);
                    }
                }
            }
            if (nk < 8) {
                char* d0 = zs[nk & 1][0];
                char* d1 = zs[nk & 1][1];
                #pragma unroll
                for (int it = 0; it < 2; ++it) {
                    int u = tid + it * 512;
                    int row = u >> 4, k0 = (u & 15) * 4;
                    float4 v = (it == 0) ? p0 : p1;
                    float hx = __bfloat162float(__float2bfloat16_rn(v.x));
                    float hy = __bfloat162float(__float2bfloat16_rn(v.y));
                    float hz = __bfloat162float(__float2bfloat16_rn(v.z));
                    float hw = __bfloat162float(__float2bfloat16_rn(v.w));
                    *(uint2*)(d0 + row * ZP + k0 * 2) = make_uint2(pack2(hx, hy), pack2(hz, hw));
                    *(uint2*)(d1 + row * ZP + k0 * 2) =
                        make_uint2(pack2(v.x - hx, v.y - hy), pack2(v.z - hz, v.w - hw));
                }
            }
            __syncthreads();
        }
        float* gp = g_gx + (((long)t * 128 + cid) * 16 + wid) * 256;
        #pragma unroll
        for (int n2 = 0; n2 < 2; ++n2)
            *(float4*)(gp + n2 * 128 + lane * 4) =
                make_float4(acc[n2][0], acc[n2][1], acc[n2][2], acc[n2][3]);
    }
}

// ---- phase 2: recurrence, h-half GEMM only ----
__global__ void __launch_bounds__(NTH, 1) lstm_loop(float* __restrict__ out) {
    __shared__ __align__(16) char zs[2][2][64 * ZP];
    float* Gs = (float*)&zs[0][0][0];     // 64 x 68 floats

    const int tid = threadIdx.x;
    const int wid = tid >> 5;
    const int lane = tid & 31;
    const int g = lane >> 2, c4 = lane & 3;
    const int wm = wid >> 2, wn = wid & 3;
    const int mt = blockIdx.x >> 2;
    const int nt = blockIdx.x & 3;
    const int b0 = nt * 64;
    const uint4* __restrict__ wf = g_Wf + (long)(mt * 4 + wm) * 64 * 2 * 32;

    const int jl = tid & 15;
    const int brow = tid >> 4;    // 0..31
    const int jg = mt * 16 + jl;
    float c_reg[2] = {0.f, 0.f};

    for (int t = 0; t < TT; ++t) {
        const int par = t & 1, nxt = par ^ 1;

        // acc init from gx (independent of h: issue before the flag wait)
        float acc[2][4];
        {
            const float* gp = g_gx + (((long)t * 128 + blockIdx.x) * 16 + wid) * 256;
            #pragma unroll
            for (int n2 = 0; n2 < 2; ++n2) {
                float4 v = __ldcg((const float4*)(gp + n2 * 128 + lane * 4));
                acc[n2][0] = v.x; acc[n2][1] = v.y; acc[n2][2] = v.z; acc[n2][3] = v.w;
            }
        }

        if (t > 0 && tid < 32) {
            volatile unsigned* f = &g_flag[nt][tid];
            while (*f < (unsigned)t) { }
        }
        __syncthreads();

        // stage h chunk 0 (512 threads: one float4 per split each)
        {
            int r = tid >> 3, k0 = (tid & 7) * 8;
            *(float4*)(zs[0][0] + r * ZP + k0 * 2) =
                __ldcg((const float4*)(g_hhi[par] + (b0 + r) * HH + k0));
            *(float4*)(zs[0][1] + r * ZP + k0 * 2) =
                __ldcg((const float4*)(g_hlo[par] + (b0 + r) * HH + k0));
        }
        __syncthreads();

        for (int kc = 0; kc < 8; ++kc) {
            const int buf = kc & 1;
            const int nk = kc + 1;
            float4 p0, p1;
            if (nk < 8) {
                const int hk = nk * 64;
                int r = tid >> 3, k0 = (tid & 7) * 8;
                p0 = __ldcg((const float4*)(g_hhi[par] + (b0 + r) * HH + hk + k0));
                p1 = __ldcg((const float4*)(g_hlo[par] + (b0 + r) * HH + hk + k0));
            }
            {
                const uint4* wfb = wf + (long)((kc + 8) * 4) * 2 * 32;
                const char* zb0 = zs[buf][0];
                const char* zb1 = zs[buf][1];
                #pragma unroll
                for (int ks = 0; ks < 4; ++ks) {
                    uint4 Ah = __ldg(&wfb[(ks * 2 + 0) * 32 + lane]);
                    uint4 Al = __ldg(&wfb[(ks * 2 + 1) * 32 + lane]);
                    const char* zh = zb0 + ks * 32 + c4 * 4;
                    const char* zl = zb1 + ks * 32 + c4 * 4;
                    #pragma unroll
                    for (int n2 = 0; n2 < 2; ++n2) {
                        const int noff = (wn * 16 + n2 * 8 + g) * ZP;
                        unsigned bh0 = *(const unsigned*)(zh + noff);
                        unsigned bh1 = *(const unsigned*)(zh + noff + 16);
                        unsigned bl0 = *(const unsigned*)(zl + noff);
                        unsigned bl1 = *(const unsigned*)(zl + noff + 16);
                        MMA(acc[n2], Ah, bh0, bh1);
                        MMA(acc[n2], Ah, bl0, bl1);
                        MMA(acc[n2], Al, bh0, bh1);
                    }
                }
            }
            if (nk < 8) {
                char* d0 = zs[nk & 1][0];
                char* d1 = zs[nk & 1][1];
                int r = tid >> 3, k0 = (tid & 7) * 8;
                *(float4*)(d0 + r * ZP + k0 * 2) = p0;
                *(float4*)(d1 + r * ZP + k0 * 2) = p1;
            }
            __syncthreads();
        }

        // exchange gates via Gs
        #pragma unroll
        for (int n2 = 0; n2 < 2; ++n2) {
            const int col = wn * 16 + n2 * 8 + 2 * c4;
            const int row = wm * 16 + g;
            Gs[row * 68 + col] = acc[n2][0];
            Gs[row * 68 + col + 1] = acc[n2][1];
            Gs[(row + 8) * 68 + col] = acc[n2][2];
            Gs[(row + 8) * 68 + col + 1] = acc[n2][3];
        }
        __syncthreads();

        // elementwise gates + state update (biases folded in gx)
        #pragma unroll
        for (int q = 0; q < 2; ++q) {
            const int b = brow + 32 * q;
            const float iv = Gs[(0 + jl) * 68 + b];
            const float fv = Gs[(16 + jl) * 68 + b];
            const float gv = Gs[(32 + jl) * 68 + b];
            const float ov = Gs[(48 + jl) * 68 + b];
            const float c = sig_fast(fv) * c_reg[q] + sig_fast(iv) * tanh_fast(gv);
            c_reg[q] = c;
            const float h = sig_fast(ov) * tanh_fast(c);
            const long gi = (long)(b0 + b) * HH + jg;
            float hh = __bfloat162float(__float2bfloat16_rn(h));
            g_hhi[nxt][gi] = __float2bfloat16_rn(h);
            g_hlo[nxt][gi] = __float2bfloat16_rn(h - hh);
            out[(long)(b0 + b) * (TT * HH) + (long)t * HH + jg] = h;
            if (t == TT - 1) {
                out[(long)BB * TT * HH + gi] = h;
                out[(long)BB * TT * HH + (long)BB * HH + gi] = c;
            }
        }

        __threadfence();
        __syncthreads();
        if (tid == 0) atomicExch(&g_flag[nt][mt], (unsigned)(t + 1));
    }
}

extern "C" void kernel_launch(void* const* d_in, const int* in_sizes, int n_in,
                              void* d_out, int out_size) {
    const float* x   = (const float*)d_in[0];
    const float* wih = (const float*)d_in[1];
    const float* whh = (const float*)d_in[2];
    const float* bih = (const float*)d_in[3];
    const float* bhh = (const float*)d_in[4];
    float* out = (float*)d_out;
    (void)in_sizes; (void)n_in; (void)out_size;
    phase0<<<1024, 256>>>(wih, whh);
    phase1<<<2048, NTH>>>(x, bih, bhh);
    lstm_loop<<<NCTA, NTH>>>(out);
}

// round 9
// speedup vs baseline: 1.2148x; 1.2148x over previous
#include <cuda_runtime.h>
#include <cuda_bf16.h>
#include <stdint.h>
#include <math.h>

#define TT 512
#define BB 256
#define FF 512
#define HH 512
#define NCTA 128
#define NTH 256
#define ZP 144
#define PH 1040                 // loop h-staging pitch (bytes)
#define SPLIT (64 * PH)         // 66560 per split
#define LOOP_SMEM (2 * SPLIT)   // 133120

// W in mma-fragment order: [mt 32][wm 4][kstep 64][split 2][lane 32] x uint4
__device__ uint4 g_Wf[32 * 4 * 64 * 2 * 32];
// gx = x*Wih^T + biases, fragment order: [t][cid 128][wid 8] -> 512 floats
__device__ float g_gx[512L * 128 * 8 * 512];
__device__ __nv_bfloat16 g_hhi[2][BB * HH];
__device__ __nv_bfloat16 g_hlo[2][BB * HH];
__device__ unsigned g_flag[4][32];   // [nt][mt]: steps completed

__device__ __forceinline__ uint32_t smem_u32(const void* p) {
    uint32_t a;
    asm("{ .reg .u64 t; cvta.to.shared.u64 t, %1; cvt.u32.u64 %0, t; }" : "=r"(a) : "l"(p));
    return a;
}
__device__ __forceinline__ unsigned pack2(float a, float b) {
    __nv_bfloat162 t; t.x = __float2bfloat16_rn(a); t.y = __float2bfloat16_rn(b);
    return *(unsigned*)&t;
}
__device__ __forceinline__ float sig_fast(float v) {
    return __fdividef(1.0f, 1.0f + __expf(-v));
}
__device__ __forceinline__ float tanh_fast(float v) {
    float e = __expf(-2.0f * fabsf(v));
    return copysignf(__fdividef(1.0f - e, 1.0f + e), v);
}

#define MMA(c, a, b0, b1) \
    asm volatile("mma.sync.aligned.m16n8k16.row.col.f32.bf16.bf16.f32 " \
        "{%0,%1,%2,%3}, {%4,%5,%6,%7}, {%8,%9}, {%0,%1,%2,%3};" \
        : "+f"((c)[0]), "+f"((c)[1]), "+f"((c)[2]), "+f"((c)[3]) \
        : "r"((a).x), "r"((a).y), "r"((a).z), "r"((a).w), "r"(b0), "r"(b1))

#define CPASYNC16(dst, src) \
    asm volatile("cp.async.cg.shared.global [%0], [%1], 16;" :: "r"(dst), "l"(src))

// ---- phase 0: W gather/split to fragment order; zero h0; reset flags ----
__global__ void phase0(const float* __restrict__ wih, const float* __restrict__ whh) {
    long id = (long)blockIdx.x * blockDim.x + threadIdx.x;
    long stride = (long)gridDim.x * blockDim.x;
    for (long i = id; i < 32L * 4 * 64 * 2 * 32; i += stride) {
        int lane = (int)(i & 31);
        long r1 = i >> 5;
        int split = (int)(r1 & 1);
        long r2 = r1 >> 1;
        int kstep = (int)(r2 & 63);
        long r3 = r2 >> 6;
        int wm = (int)(r3 & 3);
        int mt = (int)(r3 >> 2);
        int g = lane >> 2, c4 = lane & 3;
        int ka = kstep * 16 + 2 * c4;
        float e[2][4];
        #pragma unroll
        for (int rr = 0; rr < 2; ++rr) {
            int r = wm * 16 + g + rr * 8;
            int orig = (r >> 4) * 512 + mt * 16 + (r & 15);
            #pragma unroll
            for (int kk = 0; kk < 4; ++kk) {
                int k = ka + (kk & 1) + (kk >> 1) * 8;
                float v = (k < 512) ? wih[(long)orig * 512 + k]
                                    : whh[(long)orig * 512 + k - 512];
                float hv = __bfloat162float(__float2bfloat16_rn(v));
                e[rr][kk] = split ? (v - hv) : v;
            }
        }
        uint4 o;
        o.x = pack2(e[0][0], e[0][1]);
        o.y = pack2(e[1][0], e[1][1]);
        o.z = pack2(e[0][2], e[0][3]);
        o.w = pack2(e[1][2], e[1][3]);
        g_Wf[i] = o;
    }
    __nv_bfloat16 z = __float2bfloat16_rn(0.0f);
    for (long i = id; i < (long)BB * HH; i += stride) { g_hhi[0][i] = z; g_hlo[0][i] = z; }
    if (id < 128) ((unsigned*)g_flag)[id] = 0;
}

// ---- phase 1: gx[t] = x_t * Wih^T + biases, fragment order (r7 layout) ----
__global__ void __launch_bounds__(NTH, 1) phase1(
    const float* __restrict__ x,
    const float* __restrict__ bih,
    const float* __restrict__ bhh)
{
    __shared__ __align__(16) char zs[2][2][64 * ZP];
    const int tid = threadIdx.x;
    const int wid = tid >> 5;
    const int lane = tid & 31;
    const int g = lane >> 2, c4 = lane & 3;
    const int wm = wid >> 1, wn = wid & 1;
    const int cid = blockIdx.x & 127;
    const int tg = blockIdx.x >> 7;
    const int mt = cid >> 2, nt = cid & 3;
    const int b0 = nt * 64;
    const int nb = wn * 32;
    const uint4* __restrict__ wf = g_Wf + (long)(mt * 4 + wm) * 64 * 2 * 32;

    const int r0 = wm * 16 + g, r1 = r0 + 8;
    const int o0 = (r0 >> 4) * 512 + mt * 16 + (r0 & 15);
    const int o1 = (r1 >> 4) * 512 + mt * 16 + (r1 & 15);
    const float b_r0 = bih[o0] + bhh[o0];
    const float b_r1 = bih[o1] + bhh[o1];

    for (int i = 0; i < 32; ++i) {
        const int t = tg * 32 + i;
        float acc[4][4];
        #pragma unroll
        for (int n2 = 0; n2 < 4; ++n2) {
            acc[n2][0] = b_r0; acc[n2][1] = b_r0;
            acc[n2][2] = b_r1; acc[n2][3] = b_r1;
        }
        const float* xs0 = x + ((long)t * BB + b0) * FF;
        #pragma unroll
        for (int it = 0; it < 4; ++it) {
            int u = tid + it * 256;
            int row = u >> 4, k0 = (u & 15) * 4;
            float4 v = *(const float4*)(xs0 + (long)row * FF + k0);
            float hx = __bfloat162float(__float2bfloat16_rn(v.x));
            float hy = __bfloat162float(__float2bfloat16_rn(v.y));
            float hz = __bfloat162float(__float2bfloat16_rn(v.z));
            float hw = __bfloat162float(__float2bfloat16_rn(v.w));
            *(uint2*)(zs[0][0] + row * ZP + k0 * 2) = make_uint2(pack2(hx, hy), pack2(hz, hw));
            *(uint2*)(zs[0][1] + row * ZP + k0 * 2) =
                make_uint2(pack2(v.x - hx, v.y - hy), pack2(v.z - hz, v.w - hw));
        }
        __syncthreads();

        for (int kc = 0; kc < 8; ++kc) {
            const int buf = kc & 1;
            const int nk = kc + 1;
            float4 p0, p1, p2, p3;
            if (nk < 8) {
                const float* xs = xs0 + nk * 64;
                int u0 = tid, u1 = tid + 256, u2 = tid + 512, u3 = tid + 768;
                p0 = *(const float4*)(xs + (long)(u0 >> 4) * FF + (u0 & 15) * 4);
                p1 = *(const float4*)(xs + (long)(u1 >> 4) * FF + (u1 & 15) * 4);
                p2 = *(const float4*)(xs + (long)(u2 >> 4) * FF + (u2 & 15) * 4);
                p3 = *(const float4*)(xs + (long)(u3 >> 4) * FF + (u3 & 15) * 4);
            }
            {
                const uint4* wfb = wf + (long)(kc * 4) * 2 * 32;
                const char* zb0 = zs[buf][0];
                const char* zb1 = zs[buf][1];
                #pragma unroll
                for (int ks = 0; ks < 4; ++ks) {
                    uint4 Ah = __ldg(&wfb[(ks * 2 + 0) * 32 + lane]);
                    uint4 Al = __ldg(&wfb[(ks * 2 + 1) * 32 + lane]);
                    const char* zh = zb0 + ks * 32 + c4 * 4;
                    const char* zl = zb1 + ks * 32 + c4 * 4;
                    #pragma unroll
                    for (int n2 = 0; n2 < 4; ++n2) {
                        const int noff = (nb + n2 * 8 + g) * ZP;
                        unsigned bh0 = *(const unsigned*)(zh + noff);
                        unsigned bh1 = *(const unsigned*)(zh + noff + 16);
                        unsigned bl0 = *(const unsigned*)(zl + noff);
                        unsigned bl1 = *(const unsigned*)(zl + noff + 16);
                        MMA(acc[n2], Ah, bh0, bh1);
                        MMA(acc[n2], Ah, bl0, bl1);
                        MMA(acc[n2], Al, bh0, bh1);
                    }
                }
            }
            if (nk < 8) {
                char* d0 = zs[nk & 1][0];
                char* d1 = zs[nk & 1][1];
                #pragma unroll
                for (int it = 0; it < 4; ++it) {
                    int u = tid + it * 256;
                    int row = u >> 4, k0 = (u & 15) * 4;
                    float4 v = (it == 0) ? p0 : (it == 1) ? p1 : (it == 2) ? p2 : p3;
                    float hx = __bfloat162float(__float2bfloat16_rn(v.x));
                    float hy = __bfloat162float(__float2bfloat16_rn(v.y));
                    float hz = __bfloat162float(__float2bfloat16_rn(v.z));
                    float hw = __bfloat162float(__float2bfloat16_rn(v.w));
                    *(uint2*)(d0 + row * ZP + k0 * 2) = make_uint2(pack2(hx, hy), pack2(hz, hw));
                    *(uint2*)(d1 + row * ZP + k0 * 2) =
                        make_uint2(pack2(v.x - hx, v.y - hy), pack2(v.z - hz, v.w - hw));
                }
            }
            __syncthreads();
        }
        float* gp = g_gx + (((long)t * 128 + cid) * 8 + wid) * 512;
        #pragma unroll
        for (int n2 = 0; n2 < 4; ++n2)
            *(float4*)(gp + n2 * 128 + lane * 4) =
                make_float4(acc[n2][0], acc[n2][1], acc[n2][2], acc[n2][3]);
    }
}

// ---- phase 2: recurrence; full-K staging, no per-chunk barriers ----
__global__ void __launch_bounds__(NTH, 1) lstm_loop(float* __restrict__ out) {
    extern __shared__ __align__(16) char sm[];
    float* Gs = (float*)sm;               // aliases split0 (guarded by barriers)

    const int tid = threadIdx.x;
    const int wid = tid >> 5;
    const int lane = tid & 31;
    const int g = lane >> 2, c4 = lane & 3;
    const int wm = wid >> 1, wn = wid & 1;
    const int mt = blockIdx.x >> 2;
    const int nt = blockIdx.x & 3;
    const int b0 = nt * 64;
    const int nb = wn * 32;
    const uint4* __restrict__ wf = g_Wf + (long)(mt * 4 + wm) * 64 * 2 * 32;
    const uint32_t zbase = smem_u32(sm);

    const int jl = tid & 15;
    const int brow = tid >> 4;
    const int jg = mt * 16 + jl;
    float c_reg[4] = {0.f, 0.f, 0.f, 0.f};

    for (int t = 0; t < TT; ++t) {
        const int par = t & 1, nxt = par ^ 1;

        // acc init from gx (independent of h: issue before the flag wait)
        float acc[4][4];
        {
            const float* gp = g_gx + (((long)t * 128 + blockIdx.x) * 8 + wid) * 512;
            #pragma unroll
            for (int n2 = 0; n2 < 4; ++n2) {
                float4 v = __ldcg((const float4*)(gp + n2 * 128 + lane * 4));
                acc[n2][0] = v.x; acc[n2][1] = v.y; acc[n2][2] = v.z; acc[n2][3] = v.w;
            }
        }

        // wait for all producers of my batch rows to finish step t-1
        if (t > 0 && tid < 32) {
            volatile unsigned* f = &g_flag[nt][tid];
            while (*f < (unsigned)t) { }
        }
        __syncthreads();

        // stage whole h tile (both splits) via cp.async: 32 x 16B per thread
        {
            const __nv_bfloat16* h0 = g_hhi[par];
            const __nv_bfloat16* h1 = g_hlo[par];
            #pragma unroll
            for (int it = 0; it < 32; ++it) {
                int i = tid + it * 256;          // [0, 8192)
                int s = i >> 12;
                int r = (i >> 6) & 63;
                int k8 = i & 63;
                const __nv_bfloat16* src = (s ? h1 : h0) + (long)(b0 + r) * HH + k8 * 8;
                CPASYNC16(zbase + s * SPLIT + r * PH + k8 * 16, src);
            }
            asm volatile("cp.async.commit_group;" ::: "memory");
            asm volatile("cp.async.wait_group 0;" ::: "memory");
        }
        __syncthreads();

        // all MMAs back-to-back, no barriers
        #pragma unroll 2
        for (int kc = 0; kc < 8; ++kc) {
            const uint4* wfb = wf + (long)((kc + 8) * 4) * 2 * 32;
            #pragma unroll
            for (int ks = 0; ks < 4; ++ks) {
                uint4 Ah = __ldg(&wfb[(ks * 2 + 0) * 32 + lane]);
                uint4 Al = __ldg(&wfb[(ks * 2 + 1) * 32 + lane]);
                const int koff = kc * 128 + ks * 32 + c4 * 4;
                #pragma unroll
                for (int n2 = 0; n2 < 4; ++n2) {
                    const int base = (nb + n2 * 8 + g) * PH + koff;
                    unsigned bh0 = *(const unsigned*)(sm + base);
                    unsigned bh1 = *(const unsigned*)(sm + base + 16);
                    unsigned bl0 = *(const unsigned*)(sm + SPLIT + base);
                    unsigned bl1 = *(const unsigned*)(sm + SPLIT + base + 16);
                    MMA(acc[n2], Ah, bh0, bh1);
                    MMA(acc[n2], Ah, bl0, bl1);
                    MMA(acc[n2], Al, bh0, bh1);
                }
            }
        }
        __syncthreads();   // all B reads done before Gs overwrite (aliases split0)

        // exchange gates via Gs
        #pragma unroll
        for (int n2 = 0; n2 < 4; ++n2) {
            const int col = nb + n2 * 8 + 2 * c4;
            const int row = wm * 16 + g;
            Gs[row * 68 + col] = acc[n2][0];
            Gs[row * 68 + col + 1] = acc[n2][1];
            Gs[(row + 8) * 68 + col] = acc[n2][2];
            Gs[(row + 8) * 68 + col + 1] = acc[n2][3];
        }
        __syncthreads();

        // elementwise gates + state update (biases folded in gx)
        #pragma unroll
        for (int q = 0; q < 4; ++q) {
            const int b = brow + 16 * q;
            const float iv = Gs[(0 + jl) * 68 + b];
            const float fv = Gs[(16 + jl) * 68 + b];
            const float gv = Gs[(32 + jl) * 68 + b];
            const float ov = Gs[(48 + jl) * 68 + b];
            const float c = sig_fast(fv) * c_reg[q] + sig_fast(iv) * tanh_fast(gv);
            c_reg[q] = c;
            const float h = sig_fast(ov) * tanh_fast(c);
            const long gi = (long)(b0 + b) * HH + jg;
            float hh = __bfloat162float(__float2bfloat16_rn(h));
            g_hhi[nxt][gi] = __float2bfloat16_rn(h);
            g_hlo[nxt][gi] = __float2bfloat16_rn(h - hh);
            out[(long)(b0 + b) * (TT * HH) + (long)t * HH + jg] = h;
            if (t == TT - 1) {
                out[(long)BB * TT * HH + gi] = h;
                out[(long)BB * TT * HH + (long)BB * HH + gi] = c;
            }
        }

        __threadfence();
        __syncthreads();
        if (tid == 0) atomicExch(&g_flag[nt][mt], (unsigned)(t + 1));
    }
}

extern "C" void kernel_launch(void* const* d_in, const int* in_sizes, int n_in,
                              void* d_out, int out_size) {
    const float* x   = (const float*)d_in[0];
    const float* wih = (const float*)d_in[1];
    const float* whh = (const float*)d_in[2];
    const float* bih = (const float*)d_in[3];
    const float* bhh = (const float*)d_in[4];
    float* out = (float*)d_out;
    (void)in_sizes; (void)n_in; (void)out_size;
    cudaFuncSetAttribute(lstm_loop, cudaFuncAttributeMaxDynamicSharedMemorySize, LOOP_SMEM);
    phase0<<<1024, 256>>>(wih, whh);
    phase1<<<2048, NTH>>>(x, bih, bhh);
    lstm_loop<<<NCTA, NTH, LOOP_SMEM>>>(out);
}

// round 10
// speedup vs baseline: 1.3182x; 1.0852x over previous
#include <cuda_runtime.h>
#include <cuda_bf16.h>
#include <stdint.h>
#include <math.h>

#define TT 512
#define BB 256
#define FF 512
#define HH 512
#define NCTA 128
#define ZP 144
#define PH 1040
#define SPLIT (64 * PH)            // 66560
#define XS_OFF (2 * SPLIT)         // 133120
#define GXR_OFF (XS_OFF + 36864)   // 169984
#define GXSLOT 17408               // 64*68*4
#define SMEM_TOTAL (GXR_OFF + 2 * GXSLOT)   // 204800

// W in mma-fragment order: [mt 32][wm 4][kstep 64][split 2][lane 32] x uint4
__device__ uint4 g_Wf[32 * 4 * 64 * 2 * 32];
__device__ __nv_bfloat16 g_hhi[2][BB * HH];
__device__ __nv_bfloat16 g_hlo[2][BB * HH];
__device__ unsigned g_flag[4][32];   // [nt][mt]: steps completed

__device__ __forceinline__ uint32_t smem_u32(const void* p) {
    uint32_t a;
    asm("{ .reg .u64 t; cvta.to.shared.u64 t, %1; cvt.u32.u64 %0, t; }" : "=r"(a) : "l"(p));
    return a;
}
__device__ __forceinline__ unsigned pack2(float a, float b) {
    __nv_bfloat162 t; t.x = __float2bfloat16_rn(a); t.y = __float2bfloat16_rn(b);
    return *(unsigned*)&t;
}
__device__ __forceinline__ float sig_fast(float v) {
    return __fdividef(1.0f, 1.0f + __expf(-v));
}
__device__ __forceinline__ float tanh_fast(float v) {
    float e = __expf(-2.0f * fabsf(v));
    return copysignf(__fdividef(1.0f - e, 1.0f + e), v);
}

#define MMA(c, a, b0, b1) \
    asm volatile("mma.sync.aligned.m16n8k16.row.col.f32.bf16.bf16.f32 " \
        "{%0,%1,%2,%3}, {%4,%5,%6,%7}, {%8,%9}, {%0,%1,%2,%3};" \
        : "+f"((c)[0]), "+f"((c)[1]), "+f"((c)[2]), "+f"((c)[3]) \
        : "r"((a).x), "r"((a).y), "r"((a).z), "r"((a).w), "r"(b0), "r"(b1))

#define CPASYNC16(dst, src) \
    asm volatile("cp.async.cg.shared.global [%0], [%1], 16;" :: "r"(dst), "l"(src))
#define CPCOMMIT() asm volatile("cp.async.commit_group;" ::: "memory")
#define CPWAIT(n)  asm volatile("cp.async.wait_group %0;" :: "n"(n) : "memory")
#define BAR(id)    asm volatile("bar.sync %0, 256;" :: "r"(id) : "memory")

// ---- phase 0: W gather/split to fragment order; zero h0; reset flags ----
__global__ void phase0(const float* __restrict__ wih, const float* __restrict__ whh) {
    long id = (long)blockIdx.x * blockDim.x + threadIdx.x;
    long stride = (long)gridDim.x * blockDim.x;
    for (long i = id; i < 32L * 4 * 64 * 2 * 32; i += stride) {
        int lane = (int)(i & 31);
        long r1 = i >> 5;
        int split = (int)(r1 & 1);
        long r2 = r1 >> 1;
        int kstep = (int)(r2 & 63);
        long r3 = r2 >> 6;
        int wm = (int)(r3 & 3);
        int mt = (int)(r3 >> 2);
        int g = lane >> 2, c4 = lane & 3;
        int ka = kstep * 16 + 2 * c4;
        float e[2][4];
        #pragma unroll
        for (int rr = 0; rr < 2; ++rr) {
            int r = wm * 16 + g + rr * 8;
            int orig = (r >> 4) * 512 + mt * 16 + (r & 15);
            #pragma unroll
            for (int kk = 0; kk < 4; ++kk) {
                int k = ka + (kk & 1) + (kk >> 1) * 8;
                float v = (k < 512) ? wih[(long)orig * 512 + k]
                                    : whh[(long)orig * 512 + k - 512];
                float hv = __bfloat162float(__float2bfloat16_rn(v));
                e[rr][kk] = split ? (v - hv) : v;
            }
        }
        uint4 o;
        o.x = pack2(e[0][0], e[0][1]);
        o.y = pack2(e[1][0], e[1][1]);
        o.z = pack2(e[0][2], e[0][3]);
        o.w = pack2(e[1][2], e[1][3]);
        g_Wf[i] = o;
    }
    __nv_bfloat16 z = __float2bfloat16_rn(0.0f);
    for (long i = id; i < (long)BB * HH; i += stride) { g_hhi[0][i] = z; g_hlo[0][i] = z; }
    if (id < 128) ((unsigned*)g_flag)[id] = 0;
}

// ---- fused persistent kernel: warps 0-7 recurrence, warps 8-15 gx producer ----
__global__ void __launch_bounds__(512, 1) lstm_fused(
    const float* __restrict__ x,
    const float* __restrict__ bih,
    const float* __restrict__ bhh,
    float* __restrict__ out)
{
    extern __shared__ __align__(16) char sm[];
    __shared__ unsigned sR, sC;       // gx slots produced / consumed

    const int tid = threadIdx.x;
    const int mt = blockIdx.x >> 2;
    const int nt = blockIdx.x & 3;
    const int b0 = nt * 64;

    if (tid == 0) { sR = 0; sC = 0; }
    __syncthreads();

    if (tid >= 256) {
        // ================= PRODUCER: gx[t] = x_t * Wih^T + biases =================
        const int ptid = tid - 256;
        const int wid = ptid >> 5;
        const int lane = ptid & 31;
        const int g = lane >> 2, c4 = lane & 3;
        const int wm = wid >> 1, wn = wid & 1;
        const int nb = wn * 32;
        const uint4* __restrict__ wf = g_Wf + (long)(mt * 4 + wm) * 64 * 2 * 32;

        const int r0 = wm * 16 + g, r1 = r0 + 8;
        const int o0 = (r0 >> 4) * 512 + mt * 16 + (r0 & 15);
        const int o1 = (r1 >> 4) * 512 + mt * 16 + (r1 & 15);
        const float b_r0 = bih[o0] + bhh[o0];
        const float b_r1 = bih[o1] + bhh[o1];

        for (int t = 0; t < TT; ++t) {
            if (ptid == 0) {
                volatile unsigned* c = &sC;
                while (*c + 2u <= (unsigned)t) { }
            }
            BAR(2);

            float acc[4][4];
            #pragma unroll
            for (int n2 = 0; n2 < 4; ++n2) {
                acc[n2][0] = b_r0; acc[n2][1] = b_r0;
                acc[n2][2] = b_r1; acc[n2][3] = b_r1;
            }
            const float* xs0 = x + ((long)t * BB + b0) * FF;
            #pragma unroll
            for (int it = 0; it < 4; ++it) {
                int u = ptid + it * 256;
                int row = u >> 4, k0 = (u & 15) * 4;
                float4 v = *(const float4*)(xs0 + (long)row * FF + k0);
                float hx = __bfloat162float(__float2bfloat16_rn(v.x));
                float hy = __bfloat162float(__float2bfloat16_rn(v.y));
                float hz = __bfloat162float(__float2bfloat16_rn(v.z));
                float hw = __bfloat162float(__float2bfloat16_rn(v.w));
                *(uint2*)(sm + XS_OFF + 0 * 9216 + row * ZP + k0 * 2) =
                    make_uint2(pack2(hx, hy), pack2(hz, hw));
                *(uint2*)(sm + XS_OFF + 1 * 9216 + row * ZP + k0 * 2) =
                    make_uint2(pack2(v.x - hx, v.y - hy), pack2(v.z - hz, v.w - hw));
            }
            BAR(2);

            for (int kc = 0; kc < 8; ++kc) {
                const int buf = kc & 1;
                const int nk = kc + 1;
                float4 p0, p1, p2, p3;
                if (nk < 8) {
                    const float* xs = xs0 + nk * 64;
                    int u0 = ptid, u1 = ptid + 256, u2 = ptid + 512, u3 = ptid + 768;
                    p0 = *(const float4*)(xs + (long)(u0 >> 4) * FF + (u0 & 15) * 4);
                    p1 = *(const float4*)(xs + (long)(u1 >> 4) * FF + (u1 & 15) * 4);
                    p2 = *(const float4*)(xs + (long)(u2 >> 4) * FF + (u2 & 15) * 4);
                    p3 = *(const float4*)(xs + (long)(u3 >> 4) * FF + (u3 & 15) * 4);
                }
                {
                    const uint4* wfb = wf + (long)(kc * 4) * 2 * 32;
                    const char* zb0 = sm + XS_OFF + (buf * 2 + 0) * 9216;
                    const char* zb1 = sm + XS_OFF + (buf * 2 + 1) * 9216;
                    #pragma unroll
                    for (int ks = 0; ks < 4; ++ks) {
                        uint4 Ah = __ldg(&wfb[(ks * 2 + 0) * 32 + lane]);
                        uint4 Al = __ldg(&wfb[(ks * 2 + 1) * 32 + lane]);
                        const char* zh = zb0 + ks * 32 + c4 * 4;
                        const char* zl = zb1 + ks * 32 + c4 * 4;
                        #pragma unroll
                        for (int n2 = 0; n2 < 4; ++n2) {
                            const int noff = (nb + n2 * 8 + g) * ZP;
                            unsigned bh0 = *(const unsigned*)(zh + noff);
                            unsigned bh1 = *(const unsigned*)(zh + noff + 16);
                            unsigned bl0 = *(const unsigned*)(zl + noff);
                            unsigned bl1 = *(const unsigned*)(zl + noff + 16);
                            MMA(acc[n2], Ah, bh0, bh1);
                            MMA(acc[n2], Ah, bl0, bl1);
                            MMA(acc[n2], Al, bh0, bh1);
                        }
                    }
                }
                if (nk < 8) {
                    char* d0 = sm + XS_OFF + ((nk & 1) * 2 + 0) * 9216;
                    char* d1 = sm + XS_OFF + ((nk & 1) * 2 + 1) * 9216;
                    #pragma unroll
                    for (int it = 0; it < 4; ++it) {
                        int u = ptid + it * 256;
                        int row = u >> 4, k0 = (u & 15) * 4;
                        float4 v = (it == 0) ? p0 : (it == 1) ? p1 : (it == 2) ? p2 : p3;
                        float hx = __bfloat162float(__float2bfloat16_rn(v.x));
                        float hy = __bfloat162float(__float2bfloat16_rn(v.y));
                        float hz = __bfloat162float(__float2bfloat16_rn(v.z));
                        float hw = __bfloat162float(__float2bfloat16_rn(v.w));
                        *(uint2*)(d0 + row * ZP + k0 * 2) = make_uint2(pack2(hx, hy), pack2(hz, hw));
                        *(uint2*)(d1 + row * ZP + k0 * 2) =
                            make_uint2(pack2(v.x - hx, v.y - hy), pack2(v.z - hz, v.w - hw));
                    }
                }
                BAR(2);
            }

            // write fragment to gx ring slot
            float* gq = (float*)(sm + GXR_OFF + (t & 1) * GXSLOT);
            #pragma unroll
            for (int n2 = 0; n2 < 4; ++n2) {
                const int col = nb + n2 * 8 + 2 * c4;
                const int row = wm * 16 + g;
                gq[row * 68 + col] = acc[n2][0];
                gq[row * 68 + col + 1] = acc[n2][1];
                gq[(row + 8) * 68 + col] = acc[n2][2];
                gq[(row + 8) * 68 + col + 1] = acc[n2][3];
            }
            BAR(2);
            if (ptid == 0) *(volatile unsigned*)&sR = (unsigned)(t + 1);
        }
    } else {
        // ================= CONSUMER: recurrence =================
        const int wid = tid >> 5;
        const int lane = tid & 31;
        const int g = lane >> 2, c4 = lane & 3;
        const int wm = wid >> 1, wn = wid & 1;
        const int nb = wn * 32;
        const uint4* __restrict__ wf = g_Wf + (long)(mt * 4 + wm) * 64 * 2 * 32;
        const uint32_t zbase = smem_u32(sm);
        float* Gs = (float*)sm;     // aliases h split0 (consumer-only, barrier-guarded)

        const int jl = tid & 15;
        const int brow = tid >> 4;
        const int jg = mt * 16 + jl;
        float c_reg[4] = {0.f, 0.f, 0.f, 0.f};

        for (int t = 0; t < TT; ++t) {
            const int par = t & 1, nxt = par ^ 1;

            // wait: h producers (tid<32) and gx slot (tid==32)
            if (t > 0 && tid < 32) {
                volatile unsigned* f = &g_flag[nt][tid];
                while (*f < (unsigned)t) { }
            }
            if (tid == 32) {
                volatile unsigned* r = &sR;
                while (*r <= (unsigned)t) { }
            }
            BAR(1);

            // stage h tile in 4 pipelined cp.async groups (128 cols each)
            {
                const __nv_bfloat16* h0 = g_hhi[par];
                const __nv_bfloat16* h1 = g_hlo[par];
                #pragma unroll
                for (int gb = 0; gb < 4; ++gb) {
                    #pragma unroll
                    for (int it = 0; it < 8; ++it) {
                        int i2 = tid + it * 256;          // [0, 2048)
                        int s = i2 >> 10;
                        int r = (i2 >> 4) & 63;
                        int k8 = gb * 16 + (i2 & 15);
                        const __nv_bfloat16* src = (s ? h1 : h0) + (long)(b0 + r) * HH + k8 * 8;
                        CPASYNC16(zbase + s * SPLIT + r * PH + k8 * 16, src);
                    }
                    CPCOMMIT();
                }
            }

            // acc init from gx ring (smem)
            float acc[4][4];
            {
                const float* gq = (const float*)(sm + GXR_OFF + (t & 1) * GXSLOT);
                #pragma unroll
                for (int n2 = 0; n2 < 4; ++n2) {
                    const int col = nb + n2 * 8 + 2 * c4;
                    const int row = wm * 16 + g;
                    acc[n2][0] = gq[row * 68 + col];
                    acc[n2][1] = gq[row * 68 + col + 1];
                    acc[n2][2] = gq[(row + 8) * 68 + col];
                    acc[n2][3] = gq[(row + 8) * 68 + col + 1];
                }
            }
            BAR(1);
            if (tid == 0) *(volatile unsigned*)&sC = (unsigned)(t + 1);

            // MMAs, pipelined against cp.async groups
            #pragma unroll
            for (int half = 0; half < 4; ++half) {
                if (half == 0) CPWAIT(3);
                else if (half == 1) CPWAIT(2);
                else if (half == 2) CPWAIT(1);
                else CPWAIT(0);
                BAR(1);
                #pragma unroll
                for (int kc2 = 0; kc2 < 2; ++kc2) {
                    const int kc = half * 2 + kc2;
                    const uint4* wfb = wf + (long)((kc + 8) * 4) * 2 * 32;
                    #pragma unroll
                    for (int ks = 0; ks < 4; ++ks) {
                        uint4 Ah = __ldg(&wfb[(ks * 2 + 0) * 32 + lane]);
                        uint4 Al = __ldg(&wfb[(ks * 2 + 1) * 32 + lane]);
                        const int koff = kc * 128 + ks * 32 + c4 * 4;
                        #pragma unroll
                        for (int n2 = 0; n2 < 4; ++n2) {
                            const int base = (nb + n2 * 8 + g) * PH + koff;
                            unsigned bh0 = *(const unsigned*)(sm + base);
                            unsigned bh1 = *(const unsigned*)(sm + base + 16);
                            unsigned bl0 = *(const unsigned*)(sm + SPLIT + base);
                            unsigned bl1 = *(const unsigned*)(sm + SPLIT + base + 16);
                            MMA(acc[n2], Ah, bh0, bh1);
                            MMA(acc[n2], Ah, bl0, bl1);
                            MMA(acc[n2], Al, bh0, bh1);
                        }
                    }
                }
            }
            BAR(1);   // all B reads done before Gs overwrite

            // exchange gates
            #pragma unroll
            for (int n2 = 0; n2 < 4; ++n2) {
                const int col = nb + n2 * 8 + 2 * c4;
                const int row = wm * 16 + g;
                Gs[row * 68 + col] = acc[n2][0];
                Gs[row * 68 + col + 1] = acc[n2][1];
                Gs[(row + 8) * 68 + col] = acc[n2][2];
                Gs[(row + 8) * 68 + col + 1] = acc[n2][3];
            }
            BAR(1);

            // elementwise; publish h FIRST, out stores after the flag
            float hq[4], cq[4];
            #pragma unroll
            for (int q = 0; q < 4; ++q) {
                const int b = brow + 16 * q;
                const float iv = Gs[(0 + jl) * 68 + b];
                const float fv = Gs[(16 + jl) * 68 + b];
                const float gv = Gs[(32 + jl) * 68 + b];
                const float ov = Gs[(48 + jl) * 68 + b];
                const float c = sig_fast(fv) * c_reg[q] + sig_fast(iv) * tanh_fast(gv);
                c_reg[q] = c; cq[q] = c;
                const float h = sig_fast(ov) * tanh_fast(c);
                hq[q] = h;
                const long gi = (long)(b0 + b) * HH + jg;
                float hh = __bfloat162float(__float2bfloat16_rn(h));
                g_hhi[nxt][gi] = __float2bfloat16_rn(h);
                g_hlo[nxt][gi] = __float2bfloat16_rn(h - hh);
            }
            __threadfence();
            BAR(1);
            if (tid == 0) atomicExch(&g_flag[nt][mt], (unsigned)(t + 1));

            #pragma unroll
            for (int q = 0; q < 4; ++q) {
                const int b = brow + 16 * q;
                out[(long)(b0 + b) * (TT * HH) + (long)t * HH + jg] = hq[q];
                if (t == TT - 1) {
                    const long gi = (long)(b0 + b) * HH + jg;
                    out[(long)BB * TT * HH + gi] = hq[q];
                    out[(long)BB * TT * HH + (long)BB * HH + gi] = cq[q];
                }
            }
        }
    }
}

extern "C" void kernel_launch(void* const* d_in, const int* in_sizes, int n_in,
                              void* d_out, int out_size) {
    const float* x   = (const float*)d_in[0];
    const float* wih = (const float*)d_in[1];
    const float* whh = (const float*)d_in[2];
    const float* bih = (const float*)d_in[3];
    const float* bhh = (const float*)d_in[4];
    float* out = (float*)d_out;
    (void)in_sizes; (void)n_in; (void)out_size;
    cudaFuncSetAttribute(lstm_fused, cudaFuncAttributeMaxDynamicSharedMemorySize, SMEM_TOTAL);
    phase0<<<1024, 256>>>(wih, whh);
    lstm_fused<<<NCTA, 512, SMEM_TOTAL>>>(x, bih, bhh, out);
}

// round 11
// speedup vs baseline: 1.3623x; 1.0335x over previous
#include <cuda_runtime.h>
#include <cuda_bf16.h>
#include <stdint.h>
#include <math.h>

#define TT 512
#define BB 256
#define FF 512
#define HH 512
#define NCTA 128
#define ZP 144
#define PH 1040
#define SPLIT (64 * PH)            // 66560
#define XS_OFF (2 * SPLIT)         // 133120
#define GXR_OFF (XS_OFF + 36864)   // 169984
#define GXSLOT 17408               // 64*68*4
#define SMEM_TOTAL (GXR_OFF + 2 * GXSLOT)   // 204800

// W in mma-fragment order: [mt 32][wm 4][kstep 64][split 2][lane 32] x uint4
__device__ uint4 g_Wf[32 * 4 * 64 * 2 * 32];
// x pre-split to bf16 hi/lo, chunk blocks: [t][nt][kc][split][64r][64c] (16KB/blk)
__device__ uint8_t g_xs[512L * 4 * 8 * 16384];
__device__ __nv_bfloat16 g_hhi[2][BB * HH];
__device__ __nv_bfloat16 g_hlo[2][BB * HH];
__device__ unsigned g_flag[4][32];   // [nt][mt]: steps completed

__device__ __forceinline__ uint32_t smem_u32(const void* p) {
    uint32_t a;
    asm("{ .reg .u64 t; cvta.to.shared.u64 t, %1; cvt.u32.u64 %0, t; }" : "=r"(a) : "l"(p));
    return a;
}
__device__ __forceinline__ unsigned pack2(float a, float b) {
    __nv_bfloat162 t; t.x = __float2bfloat16_rn(a); t.y = __float2bfloat16_rn(b);
    return *(unsigned*)&t;
}
__device__ __forceinline__ float sig_fast(float v) {
    return __fdividef(1.0f, 1.0f + __expf(-v));
}
__device__ __forceinline__ float tanh_fast(float v) {
    float e = __expf(-2.0f * fabsf(v));
    return copysignf(__fdividef(1.0f - e, 1.0f + e), v);
}

#define MMA(c, a, b0, b1) \
    asm volatile("mma.sync.aligned.m16n8k16.row.col.f32.bf16.bf16.f32 " \
        "{%0,%1,%2,%3}, {%4,%5,%6,%7}, {%8,%9}, {%0,%1,%2,%3};" \
        : "+f"((c)[0]), "+f"((c)[1]), "+f"((c)[2]), "+f"((c)[3]) \
        : "r"((a).x), "r"((a).y), "r"((a).z), "r"((a).w), "r"(b0), "r"(b1))

#define CPASYNC16(dst, src) \
    asm volatile("cp.async.cg.shared.global [%0], [%1], 16;" :: "r"(dst), "l"(src))
#define CPCOMMIT() asm volatile("cp.async.commit_group;" ::: "memory")
#define CPWAIT(n)  asm volatile("cp.async.wait_group %0;" :: "n"(n) : "memory")
#define BAR(id)    asm volatile("bar.sync %0, 256;" :: "r"(id) : "memory")

// ---- phase 0: W gather/split to fragment order; zero h0; reset flags ----
__global__ void phase0(const float* __restrict__ wih, const float* __restrict__ whh) {
    long id = (long)blockIdx.x * blockDim.x + threadIdx.x;
    long stride = (long)gridDim.x * blockDim.x;
    for (long i = id; i < 32L * 4 * 64 * 2 * 32; i += stride) {
        int lane = (int)(i & 31);
        long r1 = i >> 5;
        int split = (int)(r1 & 1);
        long r2 = r1 >> 1;
        int kstep = (int)(r2 & 63);
        long r3 = r2 >> 6;
        int wm = (int)(r3 & 3);
        int mt = (int)(r3 >> 2);
        int g = lane >> 2, c4 = lane & 3;
        int ka = kstep * 16 + 2 * c4;
        float e[2][4];
        #pragma unroll
        for (int rr = 0; rr < 2; ++rr) {
            int r = wm * 16 + g + rr * 8;
            int orig = (r >> 4) * 512 + mt * 16 + (r & 15);
            #pragma unroll
            for (int kk = 0; kk < 4; ++kk) {
                int k = ka + (kk & 1) + (kk >> 1) * 8;
                float v = (k < 512) ? wih[(long)orig * 512 + k]
                                    : whh[(long)orig * 512 + k - 512];
                float hv = __bfloat162float(__float2bfloat16_rn(v));
                e[rr][kk] = split ? (v - hv) : v;
            }
        }
        uint4 o;
        o.x = pack2(e[0][0], e[0][1]);
        o.y = pack2(e[1][0], e[1][1]);
        o.z = pack2(e[0][2], e[0][3]);
        o.w = pack2(e[1][2], e[1][3]);
        g_Wf[i] = o;
    }
    __nv_bfloat16 z = __float2bfloat16_rn(0.0f);
    for (long i = id; i < (long)BB * HH; i += stride) { g_hhi[0][i] = z; g_hlo[0][i] = z; }
    if (id < 128) ((unsigned*)g_flag)[id] = 0;
}

// ---- phase X: pre-split x into bf16 hi/lo chunk blocks ----
__global__ void phaseX(const float* __restrict__ x) {
    long stride = (long)gridDim.x * blockDim.x;
    for (long id = (long)blockIdx.x * blockDim.x + threadIdx.x;
         id < 8388608L; id += stride) {
        int k8 = (int)(id & 7);
        int r  = (int)((id >> 3) & 63);
        int kc = (int)((id >> 9) & 7);
        int nt = (int)((id >> 12) & 3);
        long t = id >> 14;
        const float* src = x + ((t * 256) + nt * 64 + r) * 512L + kc * 64 + k8 * 8;
        float4 a = *(const float4*)src;
        float4 b = *(const float4*)(src + 4);
        float h0 = __bfloat162float(__float2bfloat16_rn(a.x));
        float h1 = __bfloat162float(__float2bfloat16_rn(a.y));
        float h2 = __bfloat162float(__float2bfloat16_rn(a.z));
        float h3 = __bfloat162float(__float2bfloat16_rn(a.w));
        float h4 = __bfloat162float(__float2bfloat16_rn(b.x));
        float h5 = __bfloat162float(__float2bfloat16_rn(b.y));
        float h6 = __bfloat162float(__float2bfloat16_rn(b.z));
        float h7 = __bfloat162float(__float2bfloat16_rn(b.w));
        uint4 hi = make_uint4(pack2(h0, h1), pack2(h2, h3), pack2(h4, h5), pack2(h6, h7));
        uint4 lo = make_uint4(pack2(a.x - h0, a.y - h1), pack2(a.z - h2, a.w - h3),
                              pack2(b.x - h4, b.y - h5), pack2(b.z - h6, b.w - h7));
        long blk = (t * 4 + nt) * 8 + kc;
        *(uint4*)(g_xs + blk * 16384 + r * 128 + k8 * 16) = hi;
        *(uint4*)(g_xs + blk * 16384 + 8192 + r * 128 + k8 * 16) = lo;
    }
}

// ---- fused persistent kernel: warps 0-7 recurrence, warps 8-15 gx producer ----
__global__ void __launch_bounds__(512, 1) lstm_fused(
    const float* __restrict__ bih,
    const float* __restrict__ bhh,
    float* __restrict__ out)
{
    extern __shared__ __align__(16) char sm[];
    __shared__ unsigned sR, sC;

    const int tid = threadIdx.x;
    const int mt = blockIdx.x >> 2;
    const int nt = blockIdx.x & 3;
    const int b0 = nt * 64;

    if (tid == 0) { sR = 0; sC = 0; }
    __syncthreads();

    if (tid >= 256) {
        // ================= PRODUCER: gx[t] = x_t * Wih^T + biases =================
        const int ptid = tid - 256;
        const int lane = ptid & 31;
        const int g = lane >> 2, c4 = lane & 3;
        const int wid = ptid >> 5;
        const int wm = wid >> 1, wn = wid & 1;
        const int nb = wn * 32;
        const uint4* __restrict__ wf = g_Wf + (long)(mt * 4 + wm) * 64 * 2 * 32;

        const int r0 = wm * 16 + g, r1 = r0 + 8;
        const int o0 = (r0 >> 4) * 512 + mt * 16 + (r0 & 15);
        const int o1 = (r1 >> 4) * 512 + mt * 16 + (r1 & 15);
        const float b_r0 = bih[o0] + bhh[o0];
        const float b_r1 = bih[o1] + bhh[o1];

        // per-thread copy indices (same for every chunk)
        const int ci_s = ptid >> 9;            // always 0 for ptid<256; use i-form below
        (void)ci_s;

        for (int t = 0; t < TT; ++t) {
            if (ptid == 0) {
                volatile unsigned* c = &sC;
                while (*c + 2u <= (unsigned)t) { }
            }
            BAR(2);

            float acc[4][4];
            #pragma unroll
            for (int n2 = 0; n2 < 4; ++n2) {
                acc[n2][0] = b_r0; acc[n2][1] = b_r0;
                acc[n2][2] = b_r1; acc[n2][3] = b_r1;
            }
            const uint8_t* xb = g_xs + (((long)t * 4 + nt) * 8) * 16384;

            // stage chunk 0: straight uint4 copy of pre-split x
            #pragma unroll
            for (int it = 0; it < 4; ++it) {
                int i = ptid + it * 256;
                int s = i >> 9, r = (i >> 3) & 63, k8 = i & 7;
                uint4 v = __ldcg((const uint4*)(xb + s * 8192 + r * 128 + k8 * 16));
                *(uint4*)(sm + XS_OFF + s * 9216 + r * ZP + k8 * 16) = v;
            }
            BAR(2);

            for (int kc = 0; kc < 8; ++kc) {
                const int buf = kc & 1;
                uint4 pf[4];
                if (kc < 7) {
                    const uint8_t* xc = xb + (kc + 1) * 16384;
                    #pragma unroll
                    for (int it = 0; it < 4; ++it) {
                        int i = ptid + it * 256;
                        int s = i >> 9, r = (i >> 3) & 63, k8 = i & 7;
                        pf[it] = __ldcg((const uint4*)(xc + s * 8192 + r * 128 + k8 * 16));
                    }
                }
                {
                    const uint4* wfb = wf + (long)(kc * 4) * 2 * 32;
                    const char* zb0 = sm + XS_OFF + buf * 18432;
                    const char* zb1 = zb0 + 9216;
                    #pragma unroll
                    for (int ks = 0; ks < 4; ++ks) {
                        uint4 Ah = __ldg(&wfb[(ks * 2 + 0) * 32 + lane]);
                        uint4 Al = __ldg(&wfb[(ks * 2 + 1) * 32 + lane]);
                        const char* zh = zb0 + ks * 32 + c4 * 4;
                        const char* zl = zb1 + ks * 32 + c4 * 4;
                        #pragma unroll
                        for (int n2 = 0; n2 < 4; ++n2) {
                            const int noff = (nb + n2 * 8 + g) * ZP;
                            unsigned bh0 = *(const unsigned*)(zh + noff);
                            unsigned bh1 = *(const unsigned*)(zh + noff + 16);
                            unsigned bl0 = *(const unsigned*)(zl + noff);
                            unsigned bl1 = *(const unsigned*)(zl + noff + 16);
                            MMA(acc[n2], Ah, bh0, bh1);
                            MMA(acc[n2], Ah, bl0, bl1);
                            MMA(acc[n2], Al, bh0, bh1);
                        }
                    }
                }
                if (kc < 7) {
                    char* d = sm + XS_OFF + (buf ^ 1) * 18432;
                    #pragma unroll
                    for (int it = 0; it < 4; ++it) {
                        int i = ptid + it * 256;
                        int s = i >> 9, r = (i >> 3) & 63, k8 = i & 7;
                        *(uint4*)(d + s * 9216 + r * ZP + k8 * 16) = pf[it];
                    }
                }
                BAR(2);
            }

            float* gq = (float*)(sm + GXR_OFF + (t & 1) * GXSLOT);
            #pragma unroll
            for (int n2 = 0; n2 < 4; ++n2) {
                const int col = nb + n2 * 8 + 2 * c4;
                const int row = wm * 16 + g;
                gq[row * 68 + col] = acc[n2][0];
                gq[row * 68 + col + 1] = acc[n2][1];
                gq[(row + 8) * 68 + col] = acc[n2][2];
                gq[(row + 8) * 68 + col + 1] = acc[n2][3];
            }
            BAR(2);
            if (ptid == 0) *(volatile unsigned*)&sR = (unsigned)(t + 1);
        }
    } else {
        // ================= CONSUMER: recurrence =================
        const int wid = tid >> 5;
        const int lane = tid & 31;
        const int g = lane >> 2, c4 = lane & 3;
        const int wm = wid >> 1, wn = wid & 1;
        const int nb = wn * 32;
        const uint4* __restrict__ wf = g_Wf + (long)(mt * 4 + wm) * 64 * 2 * 32;
        const uint32_t zbase = smem_u32(sm);
        float* Gs = (float*)sm;

        const int jl = tid & 15;
        const int brow = tid >> 4;
        const int jg = mt * 16 + jl;
        float c_reg[4] = {0.f, 0.f, 0.f, 0.f};

        for (int t = 0; t < TT; ++t) {
            const int par = t & 1, nxt = par ^ 1;
            const __nv_bfloat16* h0p = g_hhi[par];
            const __nv_bfloat16* h1p = g_hlo[par];

            // group 0 flags + gx ring
            if (t > 0 && tid < 8) {
                volatile unsigned* f = &g_flag[nt][tid];
                while (*f < (unsigned)t) { }
            }
            if (tid == 32) {
                volatile unsigned* r = &sR;
                while (*r <= (unsigned)t) { }
            }
            BAR(1);

            // issue h group 0 (cols 0..127)
            #pragma unroll
            for (int it = 0; it < 8; ++it) {
                int i2 = tid + it * 256;
                int s = i2 >> 10, r = (i2 >> 4) & 63, k8 = i2 & 15;
                const __nv_bfloat16* src = (s ? h1p : h0p) + (long)(b0 + r) * HH + k8 * 8;
                CPASYNC16(zbase + s * SPLIT + r * PH + k8 * 16, src);
            }
            CPCOMMIT();

            // acc init from gx ring
            float acc[4][4];
            {
                const float* gq = (const float*)(sm + GXR_OFF + (t & 1) * GXSLOT);
                #pragma unroll
                for (int n2 = 0; n2 < 4; ++n2) {
                    const int col = nb + n2 * 8 + 2 * c4;
                    const int row = wm * 16 + g;
                    acc[n2][0] = gq[row * 68 + col];
                    acc[n2][1] = gq[row * 68 + col + 1];
                    acc[n2][2] = gq[(row + 8) * 68 + col];
                    acc[n2][3] = gq[(row + 8) * 68 + col + 1];
                }
            }
            BAR(1);
            if (tid == 0) *(volatile unsigned*)&sC = (unsigned)(t + 1);

            #pragma unroll
            for (int half = 0; half < 4; ++half) {
                // issue next h group gated by its 8 producers
                if (half < 3) {
                    const int gb = half + 1;
                    if (t > 0 && tid < 8) {
                        volatile unsigned* f = &g_flag[nt][gb * 8 + tid];
                        while (*f < (unsigned)t) { }
                    }
                    BAR(1);
                    #pragma unroll
                    for (int it = 0; it < 8; ++it) {
                        int i2 = tid + it * 256;
                        int s = i2 >> 10, r = (i2 >> 4) & 63, k8l = i2 & 15;
                        int k8 = gb * 16 + k8l;
                        const __nv_bfloat16* src = (s ? h1p : h0p) + (long)(b0 + r) * HH + k8 * 8;
                        CPASYNC16(zbase + s * SPLIT + r * PH + k8 * 16, src);
                    }
                    CPCOMMIT();
                    CPWAIT(1);
                } else {
                    CPWAIT(0);
                }
                BAR(1);
                #pragma unroll
                for (int kc2 = 0; kc2 < 2; ++kc2) {
                    const int kc = half * 2 + kc2;
                    const uint4* wfb = wf + (long)((kc + 8) * 4) * 2 * 32;
                    #pragma unroll
                    for (int ks = 0; ks < 4; ++ks) {
                        uint4 Ah = __ldg(&wfb[(ks * 2 + 0) * 32 + lane]);
                        uint4 Al = __ldg(&wfb[(ks * 2 + 1) * 32 + lane]);
                        const int koff = kc * 128 + ks * 32 + c4 * 4;
                        #pragma unroll
                        for (int n2 = 0; n2 < 4; ++n2) {
                            const int base = (nb + n2 * 8 + g) * PH + koff;
                            unsigned bh0 = *(const unsigned*)(sm + base);
                            unsigned bh1 = *(const unsigned*)(sm + base + 16);
                            unsigned bl0 = *(const unsigned*)(sm + SPLIT + base);
                            unsigned bl1 = *(const unsigned*)(sm + SPLIT + base + 16);
                            MMA(acc[n2], Ah, bh0, bh1);
                            MMA(acc[n2], Ah, bl0, bl1);
                            MMA(acc[n2], Al, bh0, bh1);
                        }
                    }
                }
            }
            BAR(1);

            // exchange gates
            #pragma unroll
            for (int n2 = 0; n2 < 4; ++n2) {
                const int col = nb + n2 * 8 + 2 * c4;
                const int row = wm * 16 + g;
                Gs[row * 68 + col] = acc[n2][0];
                Gs[row * 68 + col + 1] = acc[n2][1];
                Gs[(row + 8) * 68 + col] = acc[n2][2];
                Gs[(row + 8) * 68 + col + 1] = acc[n2][3];
            }
            BAR(1);

            // elementwise; publish h first, out stores after the flag
            float hq[4], cq[4];
            #pragma unroll
            for (int q = 0; q < 4; ++q) {
                const int b = brow + 16 * q;
                const float iv = Gs[(0 + jl) * 68 + b];
                const float fv = Gs[(16 + jl) * 68 + b];
                const float gv = Gs[(32 + jl) * 68 + b];
                const float ov = Gs[(48 + jl) * 68 + b];
                const float c = sig_fast(fv) * c_reg[q] + sig_fast(iv) * tanh_fast(gv);
                c_reg[q] = c; cq[q] = c;
                const float h = sig_fast(ov) * tanh_fast(c);
                hq[q] = h;
                const long gi = (long)(b0 + b) * HH + jg;
                float hh = __bfloat162float(__float2bfloat16_rn(h));
                g_hhi[nxt][gi] = __float2bfloat16_rn(h);
                g_hlo[nxt][gi] = __float2bfloat16_rn(h - hh);
            }
            __threadfence();
            BAR(1);
            if (tid == 0) atomicExch(&g_flag[nt][mt], (unsigned)(t + 1));

            #pragma unroll
            for (int q = 0; q < 4; ++q) {
                const int b = brow + 16 * q;
                out[(long)(b0 + b) * (TT * HH) + (long)t * HH + jg] = hq[q];
                if (t == TT - 1) {
                    const long gi = (long)(b0 + b) * HH + jg;
                    out[(long)BB * TT * HH + gi] = hq[q];
                    out[(long)BB * TT * HH + (long)BB * HH + gi] = cq[q];
                }
            }
        }
    }
}

extern "C" void kernel_launch(void* const* d_in, const int* in_sizes, int n_in,
                              void* d_out, int out_size) {
    const float* x   = (const float*)d_in[0];
    const float* wih = (const float*)d_in[1];
    const float* whh = (const float*)d_in[2];
    const float* bih = (const float*)d_in[3];
    const float* bhh = (const float*)d_in[4];
    float* out = (float*)d_out;
    (void)in_sizes; (void)n_in; (void)out_size;
    cudaFuncSetAttribute(lstm_fused, cudaFuncAttributeMaxDynamicSharedMemorySize, SMEM_TOTAL);
    phase0<<<1024, 256>>>(wih, whh);
    phaseX<<<4096, 256>>>(x);
    lstm_fused<<<NCTA, 512, SMEM_TOTAL>>>(bih, bhh, out);
}

// round 12
// speedup vs baseline: 1.4980x; 1.0996x over previous
#include <cuda_runtime.h>
#include <cuda_fp16.h>
#include <stdint.h>
#include <math.h>

#define TT 512
#define BB 256
#define FF 512
#define HH 512
#define NCTA 128
#define ZP 144
#define PH 1040
#define SPLIT (64 * PH)            // 66560
#define XS_OFF (2 * SPLIT)         // 133120
#define GXR_OFF (XS_OFF + 36864)   // 169984
#define GXSLOT 17408               // 64*68*4
#define SMEM_TOTAL (GXR_OFF + 2 * GXSLOT)   // 204800

// W (fp16 hi only) in mma-fragment order: [mt 32][wm 4][kstep 64][lane 32] x uint4
__device__ uint4 g_Wf[32 * 4 * 64 * 32];
// x pre-split to fp16 hi/lo, chunk blocks: [t][nt][kc][split][64r][64c] (16KB/blk)
__device__ uint8_t g_xs[512L * 4 * 8 * 16384];
__device__ __half g_hhi[2][BB * HH];
__device__ __half g_hlo[2][BB * HH];
__device__ unsigned g_flag[4][32];   // [nt][mt]: steps completed

__device__ __forceinline__ uint32_t smem_u32(const void* p) {
    uint32_t a;
    asm("{ .reg .u64 t; cvta.to.shared.u64 t, %1; cvt.u32.u64 %0, t; }" : "=r"(a) : "l"(p));
    return a;
}
__device__ __forceinline__ unsigned pack2h(float a, float b) {
    __half2 t; t.x = __float2half_rn(a); t.y = __float2half_rn(b);
    return *(unsigned*)&t;
}
__device__ __forceinline__ float sig_fast(float v) {
    return __fdividef(1.0f, 1.0f + __expf(-v));
}
__device__ __forceinline__ float tanh_fast(float v) {
    float e = __expf(-2.0f * fabsf(v));
    return copysignf(__fdividef(1.0f - e, 1.0f + e), v);
}

#define MMA(c, a, b0, b1) \
    asm volatile("mma.sync.aligned.m16n8k16.row.col.f32.f16.f16.f32 " \
        "{%0,%1,%2,%3}, {%4,%5,%6,%7}, {%8,%9}, {%0,%1,%2,%3};" \
        : "+f"((c)[0]), "+f"((c)[1]), "+f"((c)[2]), "+f"((c)[3]) \
        : "r"((a).x), "r"((a).y), "r"((a).z), "r"((a).w), "r"(b0), "r"(b1))

#define CPASYNC16(dst, src) \
    asm volatile("cp.async.cg.shared.global [%0], [%1], 16;" :: "r"(dst), "l"(src))
#define CPCOMMIT() asm volatile("cp.async.commit_group;" ::: "memory")
#define CPWAIT(n)  asm volatile("cp.async.wait_group %0;" :: "n"(n) : "memory")
#define BAR(id)    asm volatile("bar.sync %0, 256;" :: "r"(id) : "memory")

// ---- phase 0: W gather to fp16 fragment order; zero h0; reset flags ----
__global__ void phase0(const float* __restrict__ wih, const float* __restrict__ whh) {
    long id = (long)blockIdx.x * blockDim.x + threadIdx.x;
    long stride = (long)gridDim.x * blockDim.x;
    for (long i = id; i < 32L * 4 * 64 * 32; i += stride) {
        int lane = (int)(i & 31);
        int kstep = (int)((i >> 5) & 63);
        int wm = (int)((i >> 11) & 3);
        int mt = (int)(i >> 13);
        int g = lane >> 2, c4 = lane & 3;
        int ka = kstep * 16 + 2 * c4;
        float e[2][4];
        #pragma unroll
        for (int rr = 0; rr < 2; ++rr) {
            int r = wm * 16 + g + rr * 8;
            int orig = (r >> 4) * 512 + mt * 16 + (r & 15);
            #pragma unroll
            for (int kk = 0; kk < 4; ++kk) {
                int k = ka + (kk & 1) + (kk >> 1) * 8;
                e[rr][kk] = (k < 512) ? wih[(long)orig * 512 + k]
                                      : whh[(long)orig * 512 + k - 512];
            }
        }
        uint4 o;
        o.x = pack2h(e[0][0], e[0][1]);
        o.y = pack2h(e[1][0], e[1][1]);
        o.z = pack2h(e[0][2], e[0][3]);
        o.w = pack2h(e[1][2], e[1][3]);
        g_Wf[i] = o;
    }
    __half z = __float2half_rn(0.0f);
    for (long i = id; i < (long)BB * HH; i += stride) { g_hhi[0][i] = z; g_hlo[0][i] = z; }
    if (id < 128) ((unsigned*)g_flag)[id] = 0;
}

// ---- phase X: pre-split x into fp16 hi/lo chunk blocks ----
__global__ void phaseX(const float* __restrict__ x) {
    long stride = (long)gridDim.x * blockDim.x;
    for (long id = (long)blockIdx.x * blockDim.x + threadIdx.x;
         id < 8388608L; id += stride) {
        int k8 = (int)(id & 7);
        int r  = (int)((id >> 3) & 63);
        int kc = (int)((id >> 9) & 7);
        int nt = (int)((id >> 12) & 3);
        long t = id >> 14;
        const float* src = x + ((t * 256) + nt * 64 + r) * 512L + kc * 64 + k8 * 8;
        float4 a = *(const float4*)src;
        float4 b = *(const float4*)(src + 4);
        float h0 = __half2float(__float2half_rn(a.x));
        float h1 = __half2float(__float2half_rn(a.y));
        float h2 = __half2float(__float2half_rn(a.z));
        float h3 = __half2float(__float2half_rn(a.w));
        float h4 = __half2float(__float2half_rn(b.x));
        float h5 = __half2float(__float2half_rn(b.y));
        float h6 = __half2float(__float2half_rn(b.z));
        float h7 = __half2float(__float2half_rn(b.w));
        uint4 hi = make_uint4(pack2h(h0, h1), pack2h(h2, h3), pack2h(h4, h5), pack2h(h6, h7));
        uint4 lo = make_uint4(pack2h(a.x - h0, a.y - h1), pack2h(a.z - h2, a.w - h3),
                              pack2h(b.x - h4, b.y - h5), pack2h(b.z - h6, b.w - h7));
        long blk = (t * 4 + nt) * 8 + kc;
        *(uint4*)(g_xs + blk * 16384 + r * 128 + k8 * 16) = hi;
        *(uint4*)(g_xs + blk * 16384 + 8192 + r * 128 + k8 * 16) = lo;
    }
}

// ---- fused persistent kernel: warps 0-7 recurrence, warps 8-15 gx producer ----
__global__ void __launch_bounds__(512, 1) lstm_fused(
    const float* __restrict__ bih,
    const float* __restrict__ bhh,
    float* __restrict__ out)
{
    extern __shared__ __align__(16) char sm[];
    __shared__ unsigned sR, sC;

    const int tid = threadIdx.x;
    const int mt = blockIdx.x >> 2;
    const int nt = blockIdx.x & 3;
    const int b0 = nt * 64;

    if (tid == 0) { sR = 0; sC = 0; }
    __syncthreads();

    if (tid >= 256) {
        // ================= PRODUCER: gx[t] = x_t * Wih^T + biases =================
        const int ptid = tid - 256;
        const int lane = ptid & 31;
        const int g = lane >> 2, c4 = lane & 3;
        const int wid = ptid >> 5;
        const int wm = wid >> 1, wn = wid & 1;
        const int nb = wn * 32;
        const uint4* __restrict__ wf = g_Wf + (long)(mt * 4 + wm) * 64 * 32;

        const int r0 = wm * 16 + g, r1 = r0 + 8;
        const int o0 = (r0 >> 4) * 512 + mt * 16 + (r0 & 15);
        const int o1 = (r1 >> 4) * 512 + mt * 16 + (r1 & 15);
        const float b_r0 = bih[o0] + bhh[o0];
        const float b_r1 = bih[o1] + bhh[o1];

        for (int t = 0; t < TT; ++t) {
            if (ptid == 0) {
                volatile unsigned* c = &sC;
                while (*c + 2u <= (unsigned)t) { }
            }
            BAR(2);

            float acc[4][4];
            #pragma unroll
            for (int n2 = 0; n2 < 4; ++n2) {
                acc[n2][0] = b_r0; acc[n2][1] = b_r0;
                acc[n2][2] = b_r1; acc[n2][3] = b_r1;
            }
            const uint8_t* xb = g_xs + (((long)t * 4 + nt) * 8) * 16384;

            // stage chunk 0: straight uint4 copy of pre-split x
            #pragma unroll
            for (int it = 0; it < 4; ++it) {
                int i = ptid + it * 256;
                int s = i >> 9, r = (i >> 3) & 63, k8 = i & 7;
                uint4 v = __ldcg((const uint4*)(xb + s * 8192 + r * 128 + k8 * 16));
                *(uint4*)(sm + XS_OFF + s * 9216 + r * ZP + k8 * 16) = v;
            }
            BAR(2);

            for (int kc = 0; kc < 8; ++kc) {
                const int buf = kc & 1;
                uint4 pf[4];
                if (kc < 7) {
                    const uint8_t* xc = xb + (kc + 1) * 16384;
                    #pragma unroll
                    for (int it = 0; it < 4; ++it) {
                        int i = ptid + it * 256;
                        int s = i >> 9, r = (i >> 3) & 63, k8 = i & 7;
                        pf[it] = __ldcg((const uint4*)(xc + s * 8192 + r * 128 + k8 * 16));
                    }
                }
                {
                    const uint4* wfb = wf + (long)(kc * 4) * 32;
                    const char* zb0 = sm + XS_OFF + buf * 18432;
                    const char* zb1 = zb0 + 9216;
                    #pragma unroll
                    for (int ks = 0; ks < 4; ++ks) {
                        uint4 Ah = __ldg(&wfb[ks * 32 + lane]);
                        const char* zh = zb0 + ks * 32 + c4 * 4;
                        const char* zl = zb1 + ks * 32 + c4 * 4;
                        #pragma unroll
                        for (int n2 = 0; n2 < 4; ++n2) {
                            const int noff = (nb + n2 * 8 + g) * ZP;
                            unsigned bh0 = *(const unsigned*)(zh + noff);
                            unsigned bh1 = *(const unsigned*)(zh + noff + 16);
                            unsigned bl0 = *(const unsigned*)(zl + noff);
                            unsigned bl1 = *(const unsigned*)(zl + noff + 16);
                            MMA(acc[n2], Ah, bh0, bh1);
                            MMA(acc[n2], Ah, bl0, bl1);
                        }
                    }
                }
                if (kc < 7) {
                    char* d = sm + XS_OFF + (buf ^ 1) * 18432;
                    #pragma unroll
                    for (int it = 0; it < 4; ++it) {
                        int i = ptid + it * 256;
                        int s = i >> 9, r = (i >> 3) & 63, k8 = i & 7;
                        *(uint4*)(d + s * 9216 + r * ZP + k8 * 16) = pf[it];
                    }
                }
                BAR(2);
            }

            float* gq = (float*)(sm + GXR_OFF + (t & 1) * GXSLOT);
            #pragma unroll
            for (int n2 = 0; n2 < 4; ++n2) {
                const int col = nb + n2 * 8 + 2 * c4;
                const int row = wm * 16 + g;
                gq[row * 68 + col] = acc[n2][0];
                gq[row * 68 + col + 1] = acc[n2][1];
                gq[(row + 8) * 68 + col] = acc[n2][2];
                gq[(row + 8) * 68 + col + 1] = acc[n2][3];
            }
            BAR(2);
            if (ptid == 0) *(volatile unsigned*)&sR = (unsigned)(t + 1);
        }
    } else {
        // ================= CONSUMER: recurrence =================
        const int wid = tid >> 5;
        const int lane = tid & 31;
        const int g = lane >> 2, c4 = lane & 3;
        const int wm = wid >> 1, wn = wid & 1;
        const int nb = wn * 32;
        const uint4* __restrict__ wf = g_Wf + (long)(mt * 4 + wm) * 64 * 32;
        const uint32_t zbase = smem_u32(sm);
        float* Gs = (float*)sm;

        const int jl = tid & 15;
        const int brow = tid >> 4;
        const int jg = mt * 16 + jl;
        float c_reg[4] = {0.f, 0.f, 0.f, 0.f};

        for (int t = 0; t < TT; ++t) {
            const int par = t & 1, nxt = par ^ 1;
            const __half* h0p = g_hhi[par];
            const __half* h1p = g_hlo[par];

            // group 0 flags + gx ring
            if (t > 0 && tid < 8) {
                volatile unsigned* f = &g_flag[nt][tid];
                while (*f < (unsigned)t) { }
            }
            if (tid == 32) {
                volatile unsigned* r = &sR;
                while (*r <= (unsigned)t) { }
            }
            BAR(1);

            // issue h group 0 (cols 0..127)
            #pragma unroll
            for (int it = 0; it < 8; ++it) {
                int i2 = tid + it * 256;
                int s = i2 >> 10, r = (i2 >> 4) & 63, k8 = i2 & 15;
                const __half* src = (s ? h1p : h0p) + (long)(b0 + r) * HH + k8 * 8;
                CPASYNC16(zbase + s * SPLIT + r * PH + k8 * 16, src);
            }
            CPCOMMIT();

            // acc init from gx ring
            float acc[4][4];
            {
                const float* gq = (const float*)(sm + GXR_OFF + (t & 1) * GXSLOT);
                #pragma unroll
                for (int n2 = 0; n2 < 4; ++n2) {
                    const int col = nb + n2 * 8 + 2 * c4;
                    const int row = wm * 16 + g;
                    acc[n2][0] = gq[row * 68 + col];
                    acc[n2][1] = gq[row * 68 + col + 1];
                    acc[n2][2] = gq[(row + 8) * 68 + col];
                    acc[n2][3] = gq[(row + 8) * 68 + col + 1];
                }
            }
            BAR(1);
            if (tid == 0) *(volatile unsigned*)&sC = (unsigned)(t + 1);

            #pragma unroll
            for (int half = 0; half < 4; ++half) {
                if (half < 3) {
                    const int gb = half + 1;
                    if (t > 0 && tid < 8) {
                        volatile unsigned* f = &g_flag[nt][gb * 8 + tid];
                        while (*f < (unsigned)t) { }
                    }
                    BAR(1);
                    #pragma unroll
                    for (int it = 0; it < 8; ++it) {
                        int i2 = tid + it * 256;
                        int s = i2 >> 10, r = (i2 >> 4) & 63, k8l = i2 & 15;
                        int k8 = gb * 16 + k8l;
                        const __half* src = (s ? h1p : h0p) + (long)(b0 + r) * HH + k8 * 8;
                        CPASYNC16(zbase + s * SPLIT + r * PH + k8 * 16, src);
                    }
                    CPCOMMIT();
                    CPWAIT(1);
                } else {
                    CPWAIT(0);
                }
                BAR(1);
                #pragma unroll
                for (int kc2 = 0; kc2 < 2; ++kc2) {
                    const int kc = half * 2 + kc2;
                    const uint4* wfb = wf + (long)((kc + 8) * 4) * 32;
                    #pragma unroll
                    for (int ks = 0; ks < 4; ++ks) {
                        uint4 Ah = __ldg(&wfb[ks * 32 + lane]);
                        const int koff = kc * 128 + ks * 32 + c4 * 4;
                        #pragma unroll
                        for (int n2 = 0; n2 < 4; ++n2) {
                            const int base = (nb + n2 * 8 + g) * PH + koff;
                            unsigned bh0 = *(const unsigned*)(sm + base);
                            unsigned bh1 = *(const unsigned*)(sm + base + 16);
                            unsigned bl0 = *(const unsigned*)(sm + SPLIT + base);
                            unsigned bl1 = *(const unsigned*)(sm + SPLIT + base + 16);
                            MMA(acc[n2], Ah, bh0, bh1);
                            MMA(acc[n2], Ah, bl0, bl1);
                        }
                    }
                }
            }
            BAR(1);

            // exchange gates
            #pragma unroll
            for (int n2 = 0; n2 < 4; ++n2) {
                const int col = nb + n2 * 8 + 2 * c4;
                const int row = wm * 16 + g;
                Gs[row * 68 + col] = acc[n2][0];
                Gs[row * 68 + col + 1] = acc[n2][1];
                Gs[(row + 8) * 68 + col] = acc[n2][2];
                Gs[(row + 8) * 68 + col + 1] = acc[n2][3];
            }
            BAR(1);

            // elementwise; publish h first, out stores after the flag
            float hq[4], cq[4];
            #pragma unroll
            for (int q = 0; q < 4; ++q) {
                const int b = brow + 16 * q;
                const float iv = Gs[(0 + jl) * 68 + b];
                const float fv = Gs[(16 + jl) * 68 + b];
                const float gv = Gs[(32 + jl) * 68 + b];
                const float ov = Gs[(48 + jl) * 68 + b];
                const float c = sig_fast(fv) * c_reg[q] + sig_fast(iv) * tanh_fast(gv);
                c_reg[q] = c; cq[q] = c;
                const float h = sig_fast(ov) * tanh_fast(c);
                hq[q] = h;
                const long gi = (long)(b0 + b) * HH + jg;
                float hh = __half2float(__float2half_rn(h));
                g_hhi[nxt][gi] = __float2half_rn(h);
                g_hlo[nxt][gi] = __float2half_rn(h - hh);
            }
            __threadfence();
            BAR(1);
            if (tid == 0) atomicExch(&g_flag[nt][mt], (unsigned)(t + 1));

            #pragma unroll
            for (int q = 0; q < 4; ++q) {
                const int b = brow + 16 * q;
                out[(long)(b0 + b) * (TT * HH) + (long)t * HH + jg] = hq[q];
                if (t == TT - 1) {
                    const long gi = (long)(b0 + b) * HH + jg;
                    out[(long)BB * TT * HH + gi] = hq[q];
                    out[(long)BB * TT * HH + (long)BB * HH + gi] = cq[q];
                }
            }
        }
    }
}

extern "C" void kernel_launch(void* const* d_in, const int* in_sizes, int n_in,
                              void* d_out, int out_size) {
    const float* x   = (const float*)d_in[0];
    const float* wih = (const float*)d_in[1];
    const float* whh = (const float*)d_in[2];
    const float* bih = (const float*)d_in[3];
    const float* bhh = (const float*)d_in[4];
    float* out = (float*)d_out;
    (void)in_sizes; (void)n_in; (void)out_size;
    cudaFuncSetAttribute(lstm_fused, cudaFuncAttributeMaxDynamicSharedMemorySize, SMEM_TOTAL);
    phase0<<<1024, 256>>>(wih, whh);
    phaseX<<<4096, 256>>>(x);
    lstm_fused<<<NCTA, 512, SMEM_TOTAL>>>(bih, bhh, out);
}

// round 14
// speedup vs baseline: 2.1739x; 1.4512x over previous
#include <cuda_runtime.h>
#include <cuda_fp16.h>
#include <stdint.h>
#include <math.h>

#define TT 512
#define BB 256
#define FF 512
#define HH 512
#define NCTA 128
#define ZP 144
#define PH 1040
#define HSZ (64 * PH)              // 66560
#define XS_OFF HSZ                 // 66560, 2 x 9216
#define GXR_OFF (XS_OFF + 18432)   // 84992
#define GXSLOT 17408               // 64*68*4
#define SMEM_TOTAL (GXR_OFF + 2 * GXSLOT)   // 119808

// W (fp16) in mma-fragment order: [mt 32][wm 4][kstep 64][lane 32] x uint4
__device__ uint4 g_Wf[32 * 4 * 64 * 32];
// x pre-converted fp16, chunk blocks: [t][nt][kc][64r][64c] (8KB/blk)
__device__ uint8_t g_xs[512L * 4 * 8 * 8192];
__device__ __half g_h[2][BB * HH];
__device__ unsigned g_flag[4][32];   // [nt][mt]: steps completed

__device__ __forceinline__ uint32_t smem_u32(const void* p) {
    uint32_t a;
    asm("{ .reg .u64 t; cvta.to.shared.u64 t, %1; cvt.u32.u64 %0, t; }" : "=r"(a) : "l"(p));
    return a;
}
__device__ __forceinline__ unsigned pack2h(float a, float b) {
    __half2 t; t.x = __float2half_rn(a); t.y = __float2half_rn(b);
    return *(unsigned*)&t;
}
__device__ __forceinline__ float sig_fast(float v) {
    return __fdividef(1.0f, 1.0f + __expf(-v));
}
__device__ __forceinline__ float tanh_fast(float v) {
    float e = __expf(-2.0f * fabsf(v));
    return copysignf(__fdividef(1.0f - e, 1.0f + e), v);
}

#define MMA(c, a, b0, b1) \
    asm volatile("mma.sync.aligned.m16n8k16.row.col.f32.f16.f16.f32 " \
        "{%0,%1,%2,%3}, {%4,%5,%6,%7}, {%8,%9}, {%0,%1,%2,%3};" \
        : "+f"((c)[0]), "+f"((c)[1]), "+f"((c)[2]), "+f"((c)[3]) \
        : "r"((a).x), "r"((a).y), "r"((a).z), "r"((a).w), "r"(b0), "r"(b1))

#define CPASYNC16(dst, src) \
    asm volatile("cp.async.cg.shared.global [%0], [%1], 16;" :: "r"(dst), "l"(src))
#define CPCOMMIT() asm volatile("cp.async.commit_group;" ::: "memory")
#define CPWAIT(n)  asm volatile("cp.async.wait_group %0;" :: "n"(n) : "memory")
#define BAR(id)    asm volatile("bar.sync %0, 256;" :: "r"(id) : "memory")

// ---- phase 0: W gather to fp16 fragment order; zero h0; reset flags ----
__global__ void phase0(const float* __restrict__ wih, const float* __restrict__ whh) {
    long id = (long)blockIdx.x * blockDim.x + threadIdx.x;
    long stride = (long)gridDim.x * blockDim.x;
    for (long i = id; i < 32L * 4 * 64 * 32; i += stride) {
        int lane = (int)(i & 31);
        int kstep = (int)((i >> 5) & 63);
        int wm = (int)((i >> 11) & 3);
        int mt = (int)(i >> 13);
        int g = lane >> 2, c4 = lane & 3;
        int ka = kstep * 16 + 2 * c4;
        float e[2][4];
        #pragma unroll
        for (int rr = 0; rr < 2; ++rr) {
            int r = wm * 16 + g + rr * 8;
            int orig = (r >> 4) * 512 + mt * 16 + (r & 15);
            #pragma unroll
            for (int kk = 0; kk < 4; ++kk) {
                int k = ka + (kk & 1) + (kk >> 1) * 8;
                e[rr][kk] = (k < 512) ? wih[(long)orig * 512 + k]
                                      : whh[(long)orig * 512 + k - 512];
            }
        }
        uint4 o;
        o.x = pack2h(e[0][0], e[0][1]);
        o.y = pack2h(e[1][0], e[1][1]);
        o.z = pack2h(e[0][2], e[0][3]);
        o.w = pack2h(e[1][2], e[1][3]);
        g_Wf[i] = o;
    }
    __half z = __float2half_rn(0.0f);
    for (long i = id; i < (long)BB * HH; i += stride) g_h[0][i] = z;
    if (id < 128) ((unsigned*)g_flag)[id] = 0;
}

// ---- phase X: x -> fp16 chunk blocks ----
// id bits: k8[0:3) r[3:9) kc[9:12) nt[12:14) t[14:...)  => 512*16384 ids total
__global__ void phaseX(const float* __restrict__ x) {
    long stride = (long)gridDim.x * blockDim.x;
    for (long id = (long)blockIdx.x * blockDim.x + threadIdx.x;
         id < 8388608L; id += stride) {
        int k8 = (int)(id & 7);
        int r  = (int)((id >> 3) & 63);
        int kc = (int)((id >> 9) & 7);
        int nt = (int)((id >> 12) & 3);
        long t = id >> 14;
        const float* src = x + ((t * 256) + nt * 64 + r) * 512L + kc * 64 + k8 * 8;
        float4 a = *(const float4*)src;
        float4 b = *(const float4*)(src + 4);
        uint4 hi = make_uint4(pack2h(a.x, a.y), pack2h(a.z, a.w),
                              pack2h(b.x, b.y), pack2h(b.z, b.w));
        long blk = (t * 4 + nt) * 8 + kc;
        *(uint4*)(g_xs + blk * 8192 + r * 128 + k8 * 16) = hi;
    }
}

// ---- fused persistent kernel: warps 0-7 recurrence, warps 8-15 gx producer ----
__global__ void __launch_bounds__(512, 1) lstm_fused(
    const float* __restrict__ bih,
    const float* __restrict__ bhh,
    float* __restrict__ out)
{
    extern __shared__ __align__(16) char sm[];
    __shared__ unsigned sR, sC;

    const int tid = threadIdx.x;
    const int mt = blockIdx.x >> 2;
    const int nt = blockIdx.x & 3;
    const int b0 = nt * 64;

    if (tid == 0) { sR = 0; sC = 0; }
    __syncthreads();

    if (tid >= 256) {
        // ================= PRODUCER: gx[t] = x_t * Wih^T + biases =================
        const int ptid = tid - 256;
        const int lane = ptid & 31;
        const int g = lane >> 2, c4 = lane & 3;
        const int wid = ptid >> 5;
        const int wm = wid >> 1, wn = wid & 1;
        const int nb = wn * 32;
        const uint4* __restrict__ wf = g_Wf + (long)(mt * 4 + wm) * 64 * 32;

        const int r0 = wm * 16 + g, r1 = r0 + 8;
        const int o0 = (r0 >> 4) * 512 + mt * 16 + (r0 & 15);
        const int o1 = (r1 >> 4) * 512 + mt * 16 + (r1 & 15);
        const float b_r0 = bih[o0] + bhh[o0];
        const float b_r1 = bih[o1] + bhh[o1];

        for (int t = 0; t < TT; ++t) {
            if (ptid == 0) {
                volatile unsigned* c = &sC;
                while (*c + 2u <= (unsigned)t) { }
            }
            BAR(2);

            float acc[4][4];
            #pragma unroll
            for (int n2 = 0; n2 < 4; ++n2) {
                acc[n2][0] = b_r0; acc[n2][1] = b_r0;
                acc[n2][2] = b_r1; acc[n2][3] = b_r1;
            }
            const uint8_t* xb = g_xs + (((long)t * 4 + nt) * 8) * 8192;

            // stage chunk 0: straight uint4 copy of fp16 x (2 per thread)
            #pragma unroll
            for (int it = 0; it < 2; ++it) {
                int i = ptid + it * 256;
                int r = i >> 3, k8 = i & 7;
                uint4 v = __ldcg((const uint4*)(xb + r * 128 + k8 * 16));
                *(uint4*)(sm + XS_OFF + r * ZP + k8 * 16) = v;
            }
            BAR(2);

            for (int kc = 0; kc < 8; ++kc) {
                const int buf = kc & 1;
                uint4 pf[2];
                if (kc < 7) {
                    const uint8_t* xc = xb + (kc + 1) * 8192;
                    #pragma unroll
                    for (int it = 0; it < 2; ++it) {
                        int i = ptid + it * 256;
                        int r = i >> 3, k8 = i & 7;
                        pf[it] = __ldcg((const uint4*)(xc + r * 128 + k8 * 16));
                    }
                }
                {
                    const uint4* wfb = wf + (long)(kc * 4) * 32;
                    const char* zb0 = sm + XS_OFF + buf * 9216;
                    #pragma unroll
                    for (int ks = 0; ks < 4; ++ks) {
                        uint4 Ah = __ldg(&wfb[ks * 32 + lane]);
                        const char* zh = zb0 + ks * 32 + c4 * 4;
                        #pragma unroll
                        for (int n2 = 0; n2 < 4; ++n2) {
                            const int noff = (nb + n2 * 8 + g) * ZP;
                            unsigned bh0 = *(const unsigned*)(zh + noff);
                            unsigned bh1 = *(const unsigned*)(zh + noff + 16);
                            MMA(acc[n2], Ah, bh0, bh1);
                        }
                    }
                }
                if (kc < 7) {
                    char* d = sm + XS_OFF + (buf ^ 1) * 9216;
                    #pragma unroll
                    for (int it = 0; it < 2; ++it) {
                        int i = ptid + it * 256;
                        int r = i >> 3, k8 = i & 7;
                        *(uint4*)(d + r * ZP + k8 * 16) = pf[it];
                    }
                }
                BAR(2);
            }

            float* gq = (float*)(sm + GXR_OFF + (t & 1) * GXSLOT);
            #pragma unroll
            for (int n2 = 0; n2 < 4; ++n2) {
                const int col = nb + n2 * 8 + 2 * c4;
                const int row = wm * 16 + g;
                gq[row * 68 + col] = acc[n2][0];
                gq[row * 68 + col + 1] = acc[n2][1];
                gq[(row + 8) * 68 + col] = acc[n2][2];
                gq[(row + 8) * 68 + col + 1] = acc[n2][3];
            }
            BAR(2);
            if (ptid == 0) *(volatile unsigned*)&sR = (unsigned)(t + 1);
        }
    } else {
        // ================= CONSUMER: recurrence =================
        const int wid = tid >> 5;
        const int lane = tid & 31;
        const int g = lane >> 2, c4 = lane & 3;
        const int wm = wid >> 1, wn = wid & 1;
        const int nb = wn * 32;
        const uint4* __restrict__ wf = g_Wf + (long)(mt * 4 + wm) * 64 * 32;
        const uint32_t zbase = smem_u32(sm);
        float* Gs = (float*)sm;     // aliases h tile (barrier-guarded)

        const int jl = tid & 15;
        const int brow = tid >> 4;
        const int jg = mt * 16 + jl;
        float c_reg[4] = {0.f, 0.f, 0.f, 0.f};

        for (int t = 0; t < TT; ++t) {
            const int par = t & 1, nxt = par ^ 1;
            const __half* hp = g_h[par];

            // group 0 flags + gx ring
            if (t > 0 && tid < 8) {
                volatile unsigned* f = &g_flag[nt][tid];
                while (*f < (unsigned)t) { }
            }
            if (tid == 32) {
                volatile unsigned* r = &sR;
                while (*r <= (unsigned)t) { }
            }
            BAR(1);

            // issue h group 0 (cols 0..127): 4 x 16B per thread
            #pragma unroll
            for (int it = 0; it < 4; ++it) {
                int i2 = tid + it * 256;
                int r = i2 >> 4, k8 = i2 & 15;
                const __half* src = hp + (long)(b0 + r) * HH + k8 * 8;
                CPASYNC16(zbase + r * PH + k8 * 16, src);
            }
            CPCOMMIT();

            // acc init from gx ring
            float acc[4][4];
            {
                const float* gq = (const float*)(sm + GXR_OFF + (t & 1) * GXSLOT);
                #pragma unroll
                for (int n2 = 0; n2 < 4; ++n2) {
                    const int col = nb + n2 * 8 + 2 * c4;
                    const int row = wm * 16 + g;
                    acc[n2][0] = gq[row * 68 + col];
                    acc[n2][1] = gq[row * 68 + col + 1];
                    acc[n2][2] = gq[(row + 8) * 68 + col];
                    acc[n2][3] = gq[(row + 8) * 68 + col + 1];
                }
            }
            BAR(1);
            if (tid == 0) *(volatile unsigned*)&sC = (unsigned)(t + 1);

            #pragma unroll
            for (int half = 0; half < 4; ++half) {
                if (half < 3) {
                    const int gb = half + 1;
                    if (t > 0 && tid < 8) {
                        volatile unsigned* f = &g_flag[nt][gb * 8 + tid];
                        while (*f < (unsigned)t) { }
                    }
                    BAR(1);
                    #pragma unroll
                    for (int it = 0; it < 4; ++it) {
                        int i2 = tid + it * 256;
                        int r = i2 >> 4, k8l = i2 & 15;
                        int k8 = gb * 16 + k8l;
                        const __half* src = hp + (long)(b0 + r) * HH + k8 * 8;
                        CPASYNC16(zbase + r * PH + k8 * 16, src);
                    }
                    CPCOMMIT();
                    CPWAIT(1);
                } else {
                    CPWAIT(0);
                }
                BAR(1);
                #pragma unroll
                for (int kc2 = 0; kc2 < 2; ++kc2) {
                    const int kc = half * 2 + kc2;
                    const uint4* wfb = wf + (long)((kc + 8) * 4) * 32;
                    #pragma unroll
                    for (int ks = 0; ks < 4; ++ks) {
                        uint4 Ah = __ldg(&wfb[ks * 32 + lane]);
                        const int koff = kc * 128 + ks * 32 + c4 * 4;
                        #pragma unroll
                        for (int n2 = 0; n2 < 4; ++n2) {
                            const int base = (nb + n2 * 8 + g) * PH + koff;
                            unsigned bh0 = *(const unsigned*)(sm + base);
                            unsigned bh1 = *(const unsigned*)(sm + base + 16);
                            MMA(acc[n2], Ah, bh0, bh1);
                        }
                    }
                }
            }
            BAR(1);

            // exchange gates (Gs aliases h tile; all B reads complete)
            #pragma unroll
            for (int n2 = 0; n2 < 4; ++n2) {
                const int col = nb + n2 * 8 + 2 * c4;
                const int row = wm * 16 + g;
                Gs[row * 68 + col] = acc[n2][0];
                Gs[row * 68 + col + 1] = acc[n2][1];
                Gs[(row + 8) * 68 + col] = acc[n2][2];
                Gs[(row + 8) * 68 + col + 1] = acc[n2][3];
            }
            BAR(1);

            // elementwise; publish h first, out stores after the flag
            float hq[4], cq[4];
            #pragma unroll
            for (int q = 0; q < 4; ++q) {
                const int b = brow + 16 * q;
                const float iv = Gs[(0 + jl) * 68 + b];
                const float fv = Gs[(16 + jl) * 68 + b];
                const float gv = Gs[(32 + jl) * 68 + b];
                const float ov = Gs[(48 + jl) * 68 + b];
                const float c = sig_fast(fv) * c_reg[q] + sig_fast(iv) * tanh_fast(gv);
                c_reg[q] = c; cq[q] = c;
                const float h = sig_fast(ov) * tanh_fast(c);
                hq[q] = h;
                g_h[nxt][(long)(b0 + b) * HH + jg] = __float2half_rn(h);
            }
            __threadfence();
            BAR(1);
            if (tid == 0) atomicExch(&g_flag[nt][mt], (unsigned)(t + 1));

            #pragma unroll
            for (int q = 0; q < 4; ++q) {
                const int b = brow + 16 * q;
                out[(long)(b0 + b) * (TT * HH) + (long)t * HH + jg] = hq[q];
                if (t == TT - 1) {
                    const long gi = (long)(b0 + b) * HH + jg;
                    out[(long)BB * TT * HH + gi] = hq[q];
                    out[(long)BB * TT * HH + (long)BB * HH + gi] = cq[q];
                }
            }
        }
    }
}

extern "C" void kernel_launch(void* const* d_in, const int* in_sizes, int n_in,
                              void* d_out, int out_size) {
    const float* x   = (const float*)d_in[0];
    const float* wih = (const float*)d_in[1];
    const float* whh = (const float*)d_in[2];
    const float* bih = (const float*)d_in[3];
    const float* bhh = (const float*)d_in[4];
    float* out = (float*)d_out;
    (void)in_sizes; (void)n_in; (void)out_size;
    cudaFuncSetAttribute(lstm_fused, cudaFuncAttributeMaxDynamicSharedMemorySize, SMEM_TOTAL);
    phase0<<<1024, 256>>>(wih, whh);
    phaseX<<<4096, 256>>>(x);
    lstm_fused<<<NCTA, 512, SMEM_TOTAL>>>(bih, bhh, out);
}

// round 15
// speedup vs baseline: 2.5628x; 1.1789x over previous
#include <cuda_runtime.h>
#include <cuda_fp16.h>
#include <stdint.h>
#include <math.h>

#define TT 512
#define BB 256
#define FF 512
#define HH 512
#define NCTA 128
#define ZP 144
#define PH 1040
#define HSZ (64 * PH)              // 66560
#define XS_OFF HSZ                 // 66560, 2 x 9216
#define GXR_OFF (XS_OFF + 18432)   // 84992
#define GXSLOT 17408               // 64*68*4
#define SMEM_TOTAL (GXR_OFF + 2 * GXSLOT)   // 119808

// W (fp16) in mma-fragment order: [mt 32][wm 4][kstep 64][lane 32] x uint4
__device__ uint4 g_Wf[32 * 4 * 64 * 32];
// x pre-converted fp16, chunk blocks: [t][nt][kc][64r][64c] (8KB/blk)
__device__ uint8_t g_xs[512L * 4 * 8 * 8192];
__device__ __half g_h[2][BB * HH];
__device__ unsigned g_flag[4][32];   // [nt][mt]: steps completed

__device__ __forceinline__ uint32_t smem_u32(const void* p) {
    uint32_t a;
    asm("{ .reg .u64 t; cvta.to.shared.u64 t, %1; cvt.u32.u64 %0, t; }" : "=r"(a) : "l"(p));
    return a;
}
__device__ __forceinline__ unsigned pack2h(float a, float b) {
    __half2 t; t.x = __float2half_rn(a); t.y = __float2half_rn(b);
    return *(unsigned*)&t;
}
__device__ __forceinline__ float sig_fast(float v) {
    return __fdividef(1.0f, 1.0f + __expf(-v));
}
__device__ __forceinline__ float tanh_fast(float v) {
    float e = __expf(-2.0f * fabsf(v));
    return copysignf(__fdividef(1.0f - e, 1.0f + e), v);
}

#define MMA(c, a, b0, b1) \
    asm volatile("mma.sync.aligned.m16n8k16.row.col.f32.f16.f16.f32 " \
        "{%0,%1,%2,%3}, {%4,%5,%6,%7}, {%8,%9}, {%0,%1,%2,%3};" \
        : "+f"((c)[0]), "+f"((c)[1]), "+f"((c)[2]), "+f"((c)[3]) \
        : "r"((a).x), "r"((a).y), "r"((a).z), "r"((a).w), "r"(b0), "r"(b1))

#define CPASYNC16(dst, src) \
    asm volatile("cp.async.cg.shared.global [%0], [%1], 16;" :: "r"(dst), "l"(src))
#define CPCOMMIT() asm volatile("cp.async.commit_group;" ::: "memory")
#define CPWAIT(n)  asm volatile("cp.async.wait_group %0;" :: "n"(n) : "memory")
#define BAR(id)    asm volatile("bar.sync %0, 256;" :: "r"(id) : "memory")

// ---- phase 0: W gather to fp16 fragment order; zero h0; reset flags ----
__global__ void phase0(const float* __restrict__ wih, const float* __restrict__ whh) {
    long id = (long)blockIdx.x * blockDim.x + threadIdx.x;
    long stride = (long)gridDim.x * blockDim.x;
    for (long i = id; i < 32L * 4 * 64 * 32; i += stride) {
        int lane = (int)(i & 31);
        int kstep = (int)((i >> 5) & 63);
        int wm = (int)((i >> 11) & 3);
        int mt = (int)(i >> 13);
        int g = lane >> 2, c4 = lane & 3;
        int ka = kstep * 16 + 2 * c4;
        float e[2][4];
        #pragma unroll
        for (int rr = 0; rr < 2; ++rr) {
            int r = wm * 16 + g + rr * 8;
            int orig = (r >> 4) * 512 + mt * 16 + (r & 15);
            #pragma unroll
            for (int kk = 0; kk < 4; ++kk) {
                int k = ka + (kk & 1) + (kk >> 1) * 8;
                e[rr][kk] = (k < 512) ? wih[(long)orig * 512 + k]
                                      : whh[(long)orig * 512 + k - 512];
            }
        }
        uint4 o;
        o.x = pack2h(e[0][0], e[0][1]);
        o.y = pack2h(e[1][0], e[1][1]);
        o.z = pack2h(e[0][2], e[0][3]);
        o.w = pack2h(e[1][2], e[1][3]);
        g_Wf[i] = o;
    }
    __half z = __float2half_rn(0.0f);
    for (long i = id; i < (long)BB * HH; i += stride) g_h[0][i] = z;
    if (id < 128) ((unsigned*)g_flag)[id] = 0;
}

// ---- phase X: x -> fp16 chunk blocks ----
// id bits: k8[0:3) r[3:9) kc[9:12) nt[12:14) t[14:...)
__global__ void phaseX(const float* __restrict__ x) {
    long stride = (long)gridDim.x * blockDim.x;
    for (long id = (long)blockIdx.x * blockDim.x + threadIdx.x;
         id < 8388608L; id += stride) {
        int k8 = (int)(id & 7);
        int r  = (int)((id >> 3) & 63);
        int kc = (int)((id >> 9) & 7);
        int nt = (int)((id >> 12) & 3);
        long t = id >> 14;
        const float* src = x + ((t * 256) + nt * 64 + r) * 512L + kc * 64 + k8 * 8;
        float4 a = *(const float4*)src;
        float4 b = *(const float4*)(src + 4);
        uint4 hi = make_uint4(pack2h(a.x, a.y), pack2h(a.z, a.w),
                              pack2h(b.x, b.y), pack2h(b.z, b.w));
        long blk = (t * 4 + nt) * 8 + kc;
        *(uint4*)(g_xs + blk * 8192 + r * 128 + k8 * 16) = hi;
    }
}

// ---- fused persistent kernel: warps 0-7 recurrence, warps 8-15 gx producer ----
__global__ void __launch_bounds__(512, 1) lstm_fused(
    const float* __restrict__ bih,
    const float* __restrict__ bhh,
    float* __restrict__ out)
{
    extern __shared__ __align__(16) char sm[];
    __shared__ unsigned sR, sC;

    const int tid = threadIdx.x;
    const int mt = blockIdx.x >> 2;
    const int nt = blockIdx.x & 3;
    const int b0 = nt * 64;

    if (tid == 0) { sR = 0; sC = 0; }
    __syncthreads();

    if (tid >= 256) {
        // ================= PRODUCER: gx[t] = x_t * Wih^T + biases =================
        const int ptid = tid - 256;
        const int lane = ptid & 31;
        const int g = lane >> 2, c4 = lane & 3;
        const int wid = ptid >> 5;
        const int wm = wid >> 1, wn = wid & 1;
        const int nb = wn * 32;
        const uint4* __restrict__ wf = g_Wf + (long)(mt * 4 + wm) * 64 * 32;

        const int r0 = wm * 16 + g, r1 = r0 + 8;
        const int o0 = (r0 >> 4) * 512 + mt * 16 + (r0 & 15);
        const int o1 = (r1 >> 4) * 512 + mt * 16 + (r1 & 15);
        const float b_r0 = bih[o0] + bhh[o0];
        const float b_r1 = bih[o1] + bhh[o1];

        for (int t = 0; t < TT; ++t) {
            if (ptid == 0) {
                volatile unsigned* c = &sC;
                while (*c + 2u <= (unsigned)t) { }
            }
            BAR(2);

            float acc[4][4];
            #pragma unroll
            for (int n2 = 0; n2 < 4; ++n2) {
                acc[n2][0] = b_r0; acc[n2][1] = b_r0;
                acc[n2][2] = b_r1; acc[n2][3] = b_r1;
            }
            const uint8_t* xb = g_xs + (((long)t * 4 + nt) * 8) * 8192;

            #pragma unroll
            for (int it = 0; it < 2; ++it) {
                int i = ptid + it * 256;
                int r = i >> 3, k8 = i & 7;
                uint4 v = __ldcg((const uint4*)(xb + r * 128 + k8 * 16));
                *(uint4*)(sm + XS_OFF + r * ZP + k8 * 16) = v;
            }
            BAR(2);

            for (int kc = 0; kc < 8; ++kc) {
                const int buf = kc & 1;
                uint4 pf[2];
                if (kc < 7) {
                    const uint8_t* xc = xb + (kc + 1) * 8192;
                    #pragma unroll
                    for (int it = 0; it < 2; ++it) {
                        int i = ptid + it * 256;
                        int r = i >> 3, k8 = i & 7;
                        pf[it] = __ldcg((const uint4*)(xc + r * 128 + k8 * 16));
                    }
                }
                {
                    const uint4* wfb = wf + (long)(kc * 4) * 32;
                    const char* zb0 = sm + XS_OFF + buf * 9216;
                    #pragma unroll
                    for (int ks = 0; ks < 4; ++ks) {
                        uint4 Ah = __ldg(&wfb[ks * 32 + lane]);
                        const char* zh = zb0 + ks * 32 + c4 * 4;
                        #pragma unroll
                        for (int n2 = 0; n2 < 4; ++n2) {
                            const int noff = (nb + n2 * 8 + g) * ZP;
                            unsigned bh0 = *(const unsigned*)(zh + noff);
                            unsigned bh1 = *(const unsigned*)(zh + noff + 16);
                            MMA(acc[n2], Ah, bh0, bh1);
                        }
                    }
                }
                if (kc < 7) {
                    char* d = sm + XS_OFF + (buf ^ 1) * 9216;
                    #pragma unroll
                    for (int it = 0; it < 2; ++it) {
                        int i = ptid + it * 256;
                        int r = i >> 3, k8 = i & 7;
                        *(uint4*)(d + r * ZP + k8 * 16) = pf[it];
                    }
                }
                BAR(2);
            }

            float* gq = (float*)(sm + GXR_OFF + (t & 1) * GXSLOT);
            #pragma unroll
            for (int n2 = 0; n2 < 4; ++n2) {
                const int col = nb + n2 * 8 + 2 * c4;
                const int row = wm * 16 + g;
                gq[row * 68 + col] = acc[n2][0];
                gq[row * 68 + col + 1] = acc[n2][1];
                gq[(row + 8) * 68 + col] = acc[n2][2];
                gq[(row + 8) * 68 + col + 1] = acc[n2][3];
            }
            BAR(2);
            if (ptid == 0) *(volatile unsigned*)&sR = (unsigned)(t + 1);
        }
    } else {
        // ================= CONSUMER: recurrence =================
        const int wid = tid >> 5;
        const int lane = tid & 31;
        const int g = lane >> 2, c4 = lane & 3;
        const int wm = wid >> 1, wn = wid & 1;
        const int nb = wn * 32;
        const uint4* __restrict__ wf = g_Wf + (long)(mt * 4 + wm) * 64 * 32;
        const uint32_t zbase = smem_u32(sm);
        float* Gs = (float*)sm;     // aliases h tile (barrier-guarded)

        const int jl = tid & 15;
        const int brow = tid >> 4;
        const int jg = mt * 16 + jl;
        float c_reg[4] = {0.f, 0.f, 0.f, 0.f};

        for (int t = 0; t < TT; ++t) {
            const int par = t & 1, nxt = par ^ 1;
            const __half* hp = g_h[par];

            // ONE parallel wait: all 32 producer flags (lanes of warp0) + gx ring
            if (t > 0 && tid < 32) {
                volatile unsigned* f = &g_flag[nt][tid];
                while (*f < (unsigned)t) { }
            }
            if (tid == 32) {
                volatile unsigned* r = &sR;
                while (*r <= (unsigned)t) { }
            }
            BAR(1);

            // issue ALL 4 h groups back-to-back (pipelined commits)
            #pragma unroll
            for (int gb = 0; gb < 4; ++gb) {
                #pragma unroll
                for (int it = 0; it < 4; ++it) {
                    int i2 = tid + it * 256;
                    int r = i2 >> 4, k8 = gb * 16 + (i2 & 15);
                    const __half* src = hp + (long)(b0 + r) * HH + k8 * 8;
                    CPASYNC16(zbase + r * PH + k8 * 16, src);
                }
                CPCOMMIT();
            }

            // acc init from gx ring
            float acc[4][4];
            {
                const float* gq = (const float*)(sm + GXR_OFF + (t & 1) * GXSLOT);
                #pragma unroll
                for (int n2 = 0; n2 < 4; ++n2) {
                    const int col = nb + n2 * 8 + 2 * c4;
                    const int row = wm * 16 + g;
                    acc[n2][0] = gq[row * 68 + col];
                    acc[n2][1] = gq[row * 68 + col + 1];
                    acc[n2][2] = gq[(row + 8) * 68 + col];
                    acc[n2][3] = gq[(row + 8) * 68 + col + 1];
                }
            }
            BAR(1);
            if (tid == 0) *(volatile unsigned*)&sC = (unsigned)(t + 1);

            #pragma unroll
            for (int half = 0; half < 4; ++half) {
                if (half == 0) CPWAIT(3);
                else if (half == 1) CPWAIT(2);
                else if (half == 2) CPWAIT(1);
                else CPWAIT(0);
                BAR(1);
                #pragma unroll
                for (int kc2 = 0; kc2 < 2; ++kc2) {
                    const int kc = half * 2 + kc2;
                    const uint4* wfb = wf + (long)((kc + 8) * 4) * 32;
                    #pragma unroll
                    for (int ks = 0; ks < 4; ++ks) {
                        uint4 Ah = __ldg(&wfb[ks * 32 + lane]);
                        const int koff = kc * 128 + ks * 32 + c4 * 4;
                        #pragma unroll
                        for (int n2 = 0; n2 < 4; ++n2) {
                            const int base = (nb + n2 * 8 + g) * PH + koff;
                            unsigned bh0 = *(const unsigned*)(sm + base);
                            unsigned bh1 = *(const unsigned*)(sm + base + 16);
                            MMA(acc[n2], Ah, bh0, bh1);
                        }
                    }
                }
            }
            BAR(1);

            // exchange gates (Gs aliases h tile; all B reads complete)
            #pragma unroll
            for (int n2 = 0; n2 < 4; ++n2) {
                const int col = nb + n2 * 8 + 2 * c4;
                const int row = wm * 16 + g;
                Gs[row * 68 + col] = acc[n2][0];
                Gs[row * 68 + col + 1] = acc[n2][1];
                Gs[(row + 8) * 68 + col] = acc[n2][2];
                Gs[(row + 8) * 68 + col + 1] = acc[n2][3];
            }
            BAR(1);

            // elementwise; publish h first, out stores after the flag
            float hq[4], cq[4];
            #pragma unroll
            for (int q = 0; q < 4; ++q) {
                const int b = brow + 16 * q;
                const float iv = Gs[(0 + jl) * 68 + b];
                const float fv = Gs[(16 + jl) * 68 + b];
                const float gv = Gs[(32 + jl) * 68 + b];
                const float ov = Gs[(48 + jl) * 68 + b];
                const float c = sig_fast(fv) * c_reg[q] + sig_fast(iv) * tanh_fast(gv);
                c_reg[q] = c; cq[q] = c;
                const float h = sig_fast(ov) * tanh_fast(c);
                hq[q] = h;
                g_h[nxt][(long)(b0 + b) * HH + jg] = __float2half_rn(h);
            }
            __threadfence();
            BAR(1);
            if (tid == 0) atomicExch(&g_flag[nt][mt], (unsigned)(t + 1));

            #pragma unroll
            for (int q = 0; q < 4; ++q) {
                const int b = brow + 16 * q;
                out[(long)(b0 + b) * (TT * HH) + (long)t * HH + jg] = hq[q];
                if (t == TT - 1) {
                    const long gi = (long)(b0 + b) * HH + jg;
                    out[(long)BB * TT * HH + gi] = hq[q];
                    out[(long)BB * TT * HH + (long)BB * HH + gi] = cq[q];
                }
            }
        }
    }
}

extern "C" void kernel_launch(void* const* d_in, const int* in_sizes, int n_in,
                              void* d_out, int out_size) {
    const float* x   = (const float*)d_in[0];
    const float* wih = (const float*)d_in[1];
    const float* whh = (const float*)d_in[2];
    const float* bih = (const float*)d_in[3];
    const float* bhh = (const float*)d_in[4];
    float* out = (float*)d_out;
    (void)in_sizes; (void)n_in; (void)out_size;
    cudaFuncSetAttribute(lstm_fused, cudaFuncAttributeMaxDynamicSharedMemorySize, SMEM_TOTAL);
    phase0<<<1024, 256>>>(wih, whh);
    phaseX<<<4096, 256>>>(x);
    lstm_fused<<<NCTA, 512, SMEM_TOTAL>>>(bih, bhh, out);
}